// round 9
// baseline (speedup 1.0000x reference)
#include <cuda_runtime.h>
#include <cuda_fp16.h>
#include <math.h>
#include <stdint.h>

#define NT 16384      // tokens = 4 * 4096
#define DM 1024       // d_model
#define FF 1024       // d_out
#define NE 8          // experts

// GEMM tiling
#define BM 128
#define BN 256
#define BK 64
#define CHUNKS (DM / BK)      // 16

// ---- device scratch (static, allocation-free) ----
__device__ int   g_cnt[NE];
__device__ int   g_list[NE][NT];        // packed: token | (slot<<16)
__device__ float g_w[2][NT];            // gate weight per slot per token
__device__ float g_scr[2][NT][FF];      // per-slot expert outputs (128 MiB)
__device__ __align__(16) __half g_xh[(size_t)NT * DM];          // fp16 x
__device__ __align__(16) __half g_wt[(size_t)NE * FF * DM];     // [e][n][k], fp16

// ======================= aux kernels =======================
__global__ void zero_cnt_kernel() {
    if (threadIdx.x < NE) g_cnt[threadIdx.x] = 0;
}

// One warp per token: 8 dots of length 1024, warp-reduce, top-2, sigmoid, scatter.
// Also emits fp16 x (x already in registers here).
__global__ void gate_kernel(const float* __restrict__ x,
                            const float* __restrict__ Wg,
                            const float* __restrict__ bg) {
    int gwarp = (blockIdx.x * blockDim.x + threadIdx.x) >> 5;
    int lane  = threadIdx.x & 31;
    if (gwarp >= NT) return;

    const float* xr = x + (size_t)gwarp * DM;
    float xv[32];
#pragma unroll
    for (int i = 0; i < 32; i++) xv[i] = xr[lane + 32 * i];

    __half* xh = g_xh + (size_t)gwarp * DM + lane;
#pragma unroll
    for (int i = 0; i < 32; i++) xh[32 * i] = __float2half_rn(xv[i]);

    float logits[NE];
#pragma unroll
    for (int e = 0; e < NE; e++) {
        const float* wg = Wg + e * DM;
        float acc = 0.f;
#pragma unroll
        for (int i = 0; i < 32; i++) acc += xv[i] * wg[lane + 32 * i];
#pragma unroll
        for (int o = 16; o > 0; o >>= 1) acc += __shfl_xor_sync(0xffffffffu, acc, o);
        logits[e] = acc + bg[e];
    }

    if (lane == 0) {
        int b0 = 0; float v0 = logits[0];
#pragma unroll
        for (int e = 1; e < NE; e++) if (logits[e] > v0) { v0 = logits[e]; b0 = e; }
        int b1 = -1; float v1 = -INFINITY;
#pragma unroll
        for (int e = 0; e < NE; e++) if (e != b0 && logits[e] > v1) { v1 = logits[e]; b1 = e; }

        g_w[0][gwarp] = 1.f / (1.f + expf(-v0));
        g_w[1][gwarp] = 1.f / (1.f + expf(-v1));

        int p0 = atomicAdd(&g_cnt[b0], 1);
        g_list[b0][p0] = gwarp;
        int p1 = atomicAdd(&g_cnt[b1], 1);
        g_list[b1][p1] = gwarp | (1 << 16);
    }
}

// We[e][k][n] -> WT[e][n][k] (transpose, fp16), 32x32 tiles.
__global__ void split_transpose_We(const float* __restrict__ We) {
    __shared__ float tile[32][33];
    int e  = blockIdx.z;
    int k0 = blockIdx.x * 32;
    int n0 = blockIdx.y * 32;
    int tx = threadIdx.x, ty = threadIdx.y;

    const float* src = We + ((size_t)e * DM) * FF;
#pragma unroll
    for (int i = ty; i < 32; i += 8)
        tile[i][tx] = src[(size_t)(k0 + i) * FF + n0 + tx];
    __syncthreads();
#pragma unroll
    for (int i = ty; i < 32; i += 8) {
        float v = tile[tx][i];  // = We[e][k0+tx][n0+i]
        size_t di = ((size_t)e * FF + (n0 + i)) * DM + k0 + tx;
        g_wt[di] = __float2half_rn(v);
    }
}

// ======================= HMMA expert GEMM =======================
// smem layout (bytes):
//   [0,512)    s_entry (128 int)
//   [512,1024) s_w     (128 float)
//   [1024, +3*55296) 3 stages; per stage: A rows 0..127 then B rows 0..255,
//   each row 144B (128B data = BK=64 fp16, + 16B pad)
#define ROWB 144
#define ATILEB (128 * ROWB)      // 18432
#define STAGEB (384 * ROWB)      // 55296
#define SM_TILES 1024
#define SM_TOTAL (SM_TILES + 3 * STAGEB)   // 166912

__device__ __forceinline__ uint32_t smem_u32(const void* p) {
    uint32_t a;
    asm("{ .reg .u64 t; cvta.to.shared.u64 t, %1; cvt.u32.u64 %0, t; }" : "=r"(a) : "l"(p));
    return a;
}
#define CP_ASYNC16(dst, src) \
    asm volatile("cp.async.cg.shared.global [%0], [%1], 16;" :: "r"(dst), "l"(src))
#define CP_COMMIT() asm volatile("cp.async.commit_group;")
#define CP_WAIT1()  asm volatile("cp.async.wait_group 1;")
#define CP_WAIT0()  asm volatile("cp.async.wait_group 0;")

__device__ __forceinline__ void ldsm_x4(uint32_t a, uint32_t& r0, uint32_t& r1,
                                        uint32_t& r2, uint32_t& r3) {
    asm volatile("ldmatrix.sync.aligned.m8n8.x4.shared.b16 {%0,%1,%2,%3}, [%4];"
                 : "=r"(r0), "=r"(r1), "=r"(r2), "=r"(r3) : "r"(a));
}
__device__ __forceinline__ void mma16816(float* c, uint32_t a0, uint32_t a1,
                                         uint32_t a2, uint32_t a3,
                                         uint32_t b0, uint32_t b1) {
    asm volatile(
        "mma.sync.aligned.m16n8k16.row.col.f32.f16.f16.f32 "
        "{%0,%1,%2,%3}, {%4,%5,%6,%7}, {%8,%9}, {%0,%1,%2,%3};"
        : "+f"(c[0]), "+f"(c[1]), "+f"(c[2]), "+f"(c[3])
        : "r"(a0), "r"(a1), "r"(a2), "r"(a3), "r"(b0), "r"(b1));
}

__global__ void __launch_bounds__(256) expert_gemm_tc(const float* __restrict__ be) {
    extern __shared__ char smem[];
    int e   = blockIdx.z;
    int cnt = g_cnt[e];
    int m0  = blockIdx.x * BM;
    if (m0 >= cnt) return;
    int n0  = blockIdx.y * BN;

    int tid  = threadIdx.x;
    int wid  = tid >> 5;
    int lane = tid & 31;

    int*   s_entry = (int*)smem;
    float* s_w     = (float*)(smem + 512);

    // routing metadata for this row-block
    if (tid < BM) {
        int mi = m0 + tid;
        int entry = (mi < cnt) ? g_list[e][mi] : 0;
        s_entry[tid] = entry;
        s_w[tid]     = g_w[entry >> 16][entry & 0xFFFF];
    }
    __syncthreads();

    uint32_t sb = smem_u32(smem);

    // ---- cp.async mapping ----
    // A tile: thread covers row rA = tid>>1, 64B half hA = tid&1 (4 granules)
    // B tile: thread covers full row rB = tid (8 granules, 128B)
    int rA = tid >> 1;
    int hA = tid & 1;
    const char* srcA = (const char*)(g_xh + (size_t)(s_entry[rA] & 0xFFFF) * DM) + hA * 64;
    const char* srcB = (const char*)(g_wt + ((size_t)e * FF + n0 + tid) * DM);
    uint32_t dstA = sb + SM_TILES + (uint32_t)(rA * ROWB + hA * 64);
    uint32_t dstB = sb + SM_TILES + ATILEB + (uint32_t)(tid * ROWB);

#define FILL_STAGE(stoff, kbytes) do {                                             \
        uint32_t d = (stoff);                                                      \
        const char* sa = srcA + (kbytes);                                          \
        const char* sw = srcB + (kbytes);                                          \
        CP_ASYNC16(dstA + d,      sa);                                             \
        CP_ASYNC16(dstA + d + 16, sa + 16);                                        \
        CP_ASYNC16(dstA + d + 32, sa + 32);                                        \
        CP_ASYNC16(dstA + d + 48, sa + 48);                                        \
        CP_ASYNC16(dstB + d,      sw);                                             \
        CP_ASYNC16(dstB + d + 16, sw + 16);                                        \
        CP_ASYNC16(dstB + d + 32, sw + 32);                                        \
        CP_ASYNC16(dstB + d + 48, sw + 48);                                        \
        CP_ASYNC16(dstB + d + 64, sw + 64);                                        \
        CP_ASYNC16(dstB + d + 80, sw + 80);                                        \
        CP_ASYNC16(dstB + d + 96, sw + 96);                                        \
        CP_ASYNC16(dstB + d + 112, sw + 112);                                      \
        CP_COMMIT();                                                               \
    } while (0)

    // ---- ldmatrix per-lane offsets ----
    uint32_t a_lane = (uint32_t)((lane & 15) * ROWB + (lane >> 4) * 16);
    uint32_t b_lane = (uint32_t)(((lane >> 4) * 8 + (lane & 7)) * ROWB + ((lane >> 3) & 1) * 16);

    int wm = wid & 1;         // 2 warps in M (64 rows each)
    int wn = wid >> 1;        // 4 warps in N (64 cols each)
    uint32_t a_warp = a_lane + (uint32_t)(wm * 64) * ROWB;
    uint32_t b_warp = b_lane + (uint32_t)(wn * 64) * ROWB + ATILEB;

    float acc[4][8][4];
#pragma unroll
    for (int i = 0; i < 4; i++)
#pragma unroll
        for (int j = 0; j < 8; j++)
#pragma unroll
            for (int k = 0; k < 4; k++) acc[i][j][k] = 0.f;

    // prologue: stages 0,1 in flight (lookahead 2 chunks)
    FILL_STAGE(0, 0);
    FILL_STAGE(STAGEB, BK * 2);

    // double-buffered fragments
    uint32_t a[2][4][4], b[2][4][4];

#define LOAD_FRAGS(buf, Aw, Bw, kb) do {                                           \
        _Pragma("unroll")                                                          \
        for (int mt = 0; mt < 4; mt++)                                             \
            ldsm_x4((Aw) + (uint32_t)(mt * 16) * ROWB + (kb),                      \
                    a[buf][mt][0], a[buf][mt][1], a[buf][mt][2], a[buf][mt][3]);   \
        _Pragma("unroll")                                                          \
        for (int n2 = 0; n2 < 4; n2++)                                             \
            ldsm_x4((Bw) + (uint32_t)(n2 * 16) * ROWB + (kb),                      \
                    b[buf][n2][0], b[buf][n2][1], b[buf][n2][2], b[buf][n2][3]);   \
    } while (0)

#define DO_MMAS(buf) do {                                                          \
        _Pragma("unroll")                                                          \
        for (int mt = 0; mt < 4; mt++)                                             \
            _Pragma("unroll")                                                      \
            for (int n2 = 0; n2 < 4; n2++) {                                       \
                mma16816(acc[mt][n2 * 2 + 0],                                      \
                         a[buf][mt][0], a[buf][mt][1], a[buf][mt][2], a[buf][mt][3],\
                         b[buf][n2][0], b[buf][n2][1]);                            \
                mma16816(acc[mt][n2 * 2 + 1],                                      \
                         a[buf][mt][0], a[buf][mt][1], a[buf][mt][2], a[buf][mt][3],\
                         b[buf][n2][2], b[buf][n2][3]);                            \
            }                                                                      \
    } while (0)

    for (int c = 0; c < CHUNKS; ++c) {
        if (c == CHUNKS - 1) { CP_WAIT0(); } else { CP_WAIT1(); }
        __syncthreads();
        if (c + 2 < CHUNKS)
            FILL_STAGE((uint32_t)((c + 2) % 3) * STAGEB, (size_t)(c + 2) * BK * 2);

        uint32_t stage = sb + SM_TILES + (uint32_t)(c % 3) * STAGEB;
        uint32_t Aw = stage + a_warp;
        uint32_t Bw = stage + b_warp;

        // kstep 0 fragments (serial, once per chunk)
        LOAD_FRAGS(0, Aw, Bw, 0u);

#pragma unroll
        for (int s = 0; s < 4; s++) {
            int cur = s & 1;
            if (s < 3) {
                int nxt = cur ^ 1;
                uint32_t kb = (uint32_t)((s + 1) * 32);   // next kstep, 16 fp16 = 32B
                LOAD_FRAGS(nxt, Aw, Bw, kb);
            }
            DO_MMAS(cur);
        }
    }

    // ---- epilogue ----
    int qrow = lane >> 2;          // 0..7
    int qcol = (lane & 3) * 2;     // 0,2,4,6
    float2 bias2[8];
#pragma unroll
    for (int nt = 0; nt < 8; nt++) {
        int nc = n0 + wn * 64 + nt * 8 + qcol;
        bias2[nt] = make_float2(be[e * FF + nc], be[e * FF + nc + 1]);
    }
#pragma unroll
    for (int mt = 0; mt < 4; mt++) {
#pragma unroll
        for (int half = 0; half < 2; half++) {
            int mrow = wm * 64 + mt * 16 + half * 8 + qrow;
            if (m0 + mrow < cnt) {
                int entry = s_entry[mrow];
                int tok   = entry & 0xFFFF;
                int slot  = entry >> 16;
                float w   = s_w[mrow];
#pragma unroll
                for (int nt = 0; nt < 8; nt++) {
                    int nc = n0 + wn * 64 + nt * 8 + qcol;
                    float2 o;
                    o.x = (acc[mt][nt][half * 2 + 0] + bias2[nt].x) * w;
                    o.y = (acc[mt][nt][half * 2 + 1] + bias2[nt].y) * w;
                    *(float2*)&g_scr[slot][tok][nc] = o;
                }
            }
        }
    }
}

// out = scr[0] + scr[1]
__global__ void combine_kernel(float* __restrict__ out) {
    size_t j = (size_t)blockIdx.x * blockDim.x + threadIdx.x;
    const float4* a = (const float4*)g_scr[0];
    const float4* b = (const float4*)g_scr[1];
    float4 u = a[j], v = b[j];
    ((float4*)out)[j] = make_float4(u.x + v.x, u.y + v.y, u.z + v.z, u.w + v.w);
}

extern "C" void kernel_launch(void* const* d_in, const int* in_sizes, int n_in,
                              void* d_out, int out_size) {
    const float* x  = (const float*)d_in[0];   // (4,4096,1024)
    const float* Wg = (const float*)d_in[1];   // (8,1024)
    const float* bg = (const float*)d_in[2];   // (8,)
    const float* We = (const float*)d_in[3];   // (8,1024,1024)
    const float* be = (const float*)d_in[4];   // (8,1024)
    float* out = (float*)d_out;                // (4,4096,1024) f32

    zero_cnt_kernel<<<1, 32>>>();
    gate_kernel<<<NT / 8, 256>>>(x, Wg, bg);

    split_transpose_We<<<dim3(DM / 32, FF / 32, NE), dim3(32, 8)>>>(We);

    cudaFuncSetAttribute(expert_gemm_tc, cudaFuncAttributeMaxDynamicSharedMemorySize, SM_TOTAL);
    expert_gemm_tc<<<dim3(NT / BM, FF / BN, NE), 256, SM_TOTAL>>>(be);

    combine_kernel<<<(NT * FF / 4) / 256, 256>>>(out);
}

// round 10
// speedup vs baseline: 1.0977x; 1.0977x over previous
#include <cuda_runtime.h>
#include <cuda_fp16.h>
#include <math.h>
#include <stdint.h>

#define NT 16384      // tokens = 4 * 4096
#define DM 1024       // d_model
#define FF 1024       // d_out
#define NE 8          // experts

// GEMM tiling
#define BM 192
#define BN 256
#define BK 32
#define CHUNKS (DM / BK)      // 32
#define NTHREADS 384

// ---- device scratch (static, allocation-free) ----
__device__ int   g_cnt[NE];
__device__ int   g_list[NE][NT];        // packed: token | (slot<<16)
__device__ float g_w[2][NT];            // gate weight per slot per token
__device__ float g_scr[2][NT][FF];      // per-slot expert outputs (128 MiB)
__device__ __align__(16) __half g_xh[(size_t)NT * DM];          // fp16 x
__device__ __align__(16) __half g_wt[(size_t)NE * FF * DM];     // [e][n][k], fp16

// ======================= aux kernels =======================
__global__ void zero_cnt_kernel() {
    if (threadIdx.x < NE) g_cnt[threadIdx.x] = 0;
}

// One warp per token: 8 dots of length 1024, warp-reduce, top-2, sigmoid, scatter.
// Also emits fp16 x (x already in registers here).
__global__ void gate_kernel(const float* __restrict__ x,
                            const float* __restrict__ Wg,
                            const float* __restrict__ bg) {
    int gwarp = (blockIdx.x * blockDim.x + threadIdx.x) >> 5;
    int lane  = threadIdx.x & 31;
    if (gwarp >= NT) return;

    const float* xr = x + (size_t)gwarp * DM;
    float xv[32];
#pragma unroll
    for (int i = 0; i < 32; i++) xv[i] = xr[lane + 32 * i];

    __half* xh = g_xh + (size_t)gwarp * DM + lane;
#pragma unroll
    for (int i = 0; i < 32; i++) xh[32 * i] = __float2half_rn(xv[i]);

    float logits[NE];
#pragma unroll
    for (int e = 0; e < NE; e++) {
        const float* wg = Wg + e * DM;
        float acc = 0.f;
#pragma unroll
        for (int i = 0; i < 32; i++) acc += xv[i] * wg[lane + 32 * i];
#pragma unroll
        for (int o = 16; o > 0; o >>= 1) acc += __shfl_xor_sync(0xffffffffu, acc, o);
        logits[e] = acc + bg[e];
    }

    if (lane == 0) {
        int b0 = 0; float v0 = logits[0];
#pragma unroll
        for (int e = 1; e < NE; e++) if (logits[e] > v0) { v0 = logits[e]; b0 = e; }
        int b1 = -1; float v1 = -INFINITY;
#pragma unroll
        for (int e = 0; e < NE; e++) if (e != b0 && logits[e] > v1) { v1 = logits[e]; b1 = e; }

        g_w[0][gwarp] = 1.f / (1.f + expf(-v0));
        g_w[1][gwarp] = 1.f / (1.f + expf(-v1));

        int p0 = atomicAdd(&g_cnt[b0], 1);
        g_list[b0][p0] = gwarp;
        int p1 = atomicAdd(&g_cnt[b1], 1);
        g_list[b1][p1] = gwarp | (1 << 16);
    }
}

// We[e][k][n] -> WT[e][n][k] (transpose, fp16), 32x32 tiles.
__global__ void split_transpose_We(const float* __restrict__ We) {
    __shared__ float tile[32][33];
    int e  = blockIdx.z;
    int k0 = blockIdx.x * 32;
    int n0 = blockIdx.y * 32;
    int tx = threadIdx.x, ty = threadIdx.y;

    const float* src = We + ((size_t)e * DM) * FF;
#pragma unroll
    for (int i = ty; i < 32; i += 8)
        tile[i][tx] = src[(size_t)(k0 + i) * FF + n0 + tx];
    __syncthreads();
#pragma unroll
    for (int i = ty; i < 32; i += 8) {
        float v = tile[tx][i];  // = We[e][k0+tx][n0+i]
        size_t di = ((size_t)e * FF + (n0 + i)) * DM + k0 + tx;
        g_wt[di] = __float2half_rn(v);
    }
}

// ======================= HMMA expert GEMM =======================
// smem layout (bytes):
//   [0,768)     s_entry (192 int)
//   [768,1536)  s_w     (192 float)
//   [2048, +4*35840) 4 stages; per stage: A rows 0..191 then B rows 0..255,
//   each row 80B (64B data + 16B pad)
#define ROWB 80
#define ATILEB (192 * ROWB)      // 15360
#define STAGEB (448 * ROWB)      // 35840
#define SM_TILES 2048
#define SM_TOTAL (SM_TILES + 4 * STAGEB)   // 145408

__device__ __forceinline__ uint32_t smem_u32(const void* p) {
    uint32_t a;
    asm("{ .reg .u64 t; cvta.to.shared.u64 t, %1; cvt.u32.u64 %0, t; }" : "=r"(a) : "l"(p));
    return a;
}
#define CP_ASYNC16(dst, src) \
    asm volatile("cp.async.cg.shared.global [%0], [%1], 16;" :: "r"(dst), "l"(src))
#define CP_COMMIT() asm volatile("cp.async.commit_group;")
#define CP_WAIT2()  asm volatile("cp.async.wait_group 2;")
#define CP_WAIT1()  asm volatile("cp.async.wait_group 1;")
#define CP_WAIT0()  asm volatile("cp.async.wait_group 0;")

__device__ __forceinline__ void ldsm_x4(uint32_t a, uint32_t& r0, uint32_t& r1,
                                        uint32_t& r2, uint32_t& r3) {
    asm volatile("ldmatrix.sync.aligned.m8n8.x4.shared.b16 {%0,%1,%2,%3}, [%4];"
                 : "=r"(r0), "=r"(r1), "=r"(r2), "=r"(r3) : "r"(a));
}
__device__ __forceinline__ void mma16816(float* c, uint32_t a0, uint32_t a1,
                                         uint32_t a2, uint32_t a3,
                                         uint32_t b0, uint32_t b1) {
    asm volatile(
        "mma.sync.aligned.m16n8k16.row.col.f32.f16.f16.f32 "
        "{%0,%1,%2,%3}, {%4,%5,%6,%7}, {%8,%9}, {%0,%1,%2,%3};"
        : "+f"(c[0]), "+f"(c[1]), "+f"(c[2]), "+f"(c[3])
        : "r"(a0), "r"(a1), "r"(a2), "r"(a3), "r"(b0), "r"(b1));
}

__global__ void __launch_bounds__(NTHREADS) expert_gemm_tc(const float* __restrict__ be) {
    extern __shared__ char smem[];
    int e   = blockIdx.z;
    int cnt = g_cnt[e];
    int m0  = blockIdx.x * BM;
    if (m0 >= cnt) return;
    int n0  = blockIdx.y * BN;

    int tid  = threadIdx.x;
    int wid  = tid >> 5;
    int lane = tid & 31;

    int*   s_entry = (int*)smem;
    float* s_w     = (float*)(smem + 768);

    // routing metadata for this row-block
    if (tid < BM) {
        int mi = m0 + tid;
        int entry = (mi < cnt) ? g_list[e][mi] : 0;
        s_entry[tid] = entry;
        s_w[tid]     = g_w[entry >> 16][entry & 0xFFFF];
    }
    __syncthreads();

    uint32_t sb = smem_u32(smem);

    // ---- cp.async mapping ----
    // A tile (192 rows x 64B): thread t -> row t>>1, 32B half t&1 (2 granules)
    // B tile (256 rows x 64B): threads t<256 -> full row t (4 granules)
    int rA = tid >> 1;
    int hA = tid & 1;
    const char* srcA = (const char*)(g_xh + (size_t)(s_entry[rA] & 0xFFFF) * DM) + hA * 32;
    const char* srcB = (const char*)(g_wt + ((size_t)e * FF + n0 + (tid & 255)) * DM);
    uint32_t dstA = sb + SM_TILES + (uint32_t)(rA * ROWB + hA * 32);
    uint32_t dstB = sb + SM_TILES + ATILEB + (uint32_t)((tid & 255) * ROWB);
    bool doB = (tid < 256);

#define FILL_STAGE(stoff, kbytes) do {                                             \
        uint32_t d = (stoff);                                                      \
        const char* sa = srcA + (kbytes);                                          \
        CP_ASYNC16(dstA + d,      sa);                                             \
        CP_ASYNC16(dstA + d + 16, sa + 16);                                        \
        if (doB) {                                                                 \
            const char* sw = srcB + (kbytes);                                      \
            CP_ASYNC16(dstB + d,      sw);                                         \
            CP_ASYNC16(dstB + d + 16, sw + 16);                                    \
            CP_ASYNC16(dstB + d + 32, sw + 32);                                    \
            CP_ASYNC16(dstB + d + 48, sw + 48);                                    \
        }                                                                          \
        CP_COMMIT();                                                               \
    } while (0)

    // ---- ldmatrix per-lane offsets ----
    uint32_t a_lane = (uint32_t)((lane & 15) * ROWB + (lane >> 4) * 16);
    uint32_t b_lane = (uint32_t)(((lane >> 4) * 8 + (lane & 7)) * ROWB + ((lane >> 3) & 1) * 16);

    int wm = wid % 3;         // 3 warps in M (64 rows each)
    int wn = wid / 3;         // 4 warps in N (64 cols each)
    uint32_t a_warp = a_lane + (uint32_t)(wm * 64) * ROWB;
    uint32_t b_warp = b_lane + (uint32_t)(wn * 64) * ROWB + ATILEB;

    float acc[4][8][4];
#pragma unroll
    for (int i = 0; i < 4; i++)
#pragma unroll
        for (int j = 0; j < 8; j++)
#pragma unroll
            for (int k = 0; k < 4; k++) acc[i][j][k] = 0.f;

    // prologue: stages 0..2 in flight
    FILL_STAGE(0, 0);
    FILL_STAGE(STAGEB, BK * 2);
    FILL_STAGE(2 * STAGEB, 2 * BK * 2);

    for (int c = 0; c < CHUNKS; ++c) {
        if (c <= CHUNKS - 3)      { CP_WAIT2(); }
        else if (c == CHUNKS - 2) { CP_WAIT1(); }
        else                      { CP_WAIT0(); }
        __syncthreads();
        if (c + 3 < CHUNKS)
            FILL_STAGE((uint32_t)((c + 3) & 3) * STAGEB, (c + 3) * BK * 2);

        uint32_t stage = sb + SM_TILES + (uint32_t)(c & 3) * STAGEB;
        uint32_t Aw = stage + a_warp;
        uint32_t Bw = stage + b_warp;

#pragma unroll
        for (int s = 0; s < 2; s++) {
            uint32_t kb = (uint32_t)(s * 32);   // 16 fp16 = 32 bytes

            uint32_t a[4][4], b[4][4];
#pragma unroll
            for (int mt = 0; mt < 4; mt++)
                ldsm_x4(Aw + (uint32_t)(mt * 16) * ROWB + kb,
                        a[mt][0], a[mt][1], a[mt][2], a[mt][3]);
#pragma unroll
            for (int n2 = 0; n2 < 4; n2++)
                ldsm_x4(Bw + (uint32_t)(n2 * 16) * ROWB + kb,
                        b[n2][0], b[n2][1], b[n2][2], b[n2][3]);
#pragma unroll
            for (int mt = 0; mt < 4; mt++)
#pragma unroll
                for (int n2 = 0; n2 < 4; n2++) {
                    mma16816(acc[mt][n2 * 2 + 0], a[mt][0], a[mt][1], a[mt][2], a[mt][3],
                             b[n2][0], b[n2][1]);
                    mma16816(acc[mt][n2 * 2 + 1], a[mt][0], a[mt][1], a[mt][2], a[mt][3],
                             b[n2][2], b[n2][3]);
                }
        }
    }

    // ---- epilogue ----
    int qrow = lane >> 2;          // 0..7
    int qcol = (lane & 3) * 2;     // 0,2,4,6
    float2 bias2[8];
#pragma unroll
    for (int nt = 0; nt < 8; nt++) {
        int nc = n0 + wn * 64 + nt * 8 + qcol;
        bias2[nt] = make_float2(be[e * FF + nc], be[e * FF + nc + 1]);
    }
#pragma unroll
    for (int mt = 0; mt < 4; mt++) {
#pragma unroll
        for (int half = 0; half < 2; half++) {
            int mrow = wm * 64 + mt * 16 + half * 8 + qrow;
            if (m0 + mrow < cnt) {
                int entry = s_entry[mrow];
                int tok   = entry & 0xFFFF;
                int slot  = entry >> 16;
                float w   = s_w[mrow];
#pragma unroll
                for (int nt = 0; nt < 8; nt++) {
                    int nc = n0 + wn * 64 + nt * 8 + qcol;
                    float2 o;
                    o.x = (acc[mt][nt][half * 2 + 0] + bias2[nt].x) * w;
                    o.y = (acc[mt][nt][half * 2 + 1] + bias2[nt].y) * w;
                    *(float2*)&g_scr[slot][tok][nc] = o;
                }
            }
        }
    }
}

// out = scr[0] + scr[1]
__global__ void combine_kernel(float* __restrict__ out) {
    size_t j = (size_t)blockIdx.x * blockDim.x + threadIdx.x;
    const float4* a = (const float4*)g_scr[0];
    const float4* b = (const float4*)g_scr[1];
    float4 u = a[j], v = b[j];
    ((float4*)out)[j] = make_float4(u.x + v.x, u.y + v.y, u.z + v.z, u.w + v.w);
}

extern "C" void kernel_launch(void* const* d_in, const int* in_sizes, int n_in,
                              void* d_out, int out_size) {
    const float* x  = (const float*)d_in[0];   // (4,4096,1024)
    const float* Wg = (const float*)d_in[1];   // (8,1024)
    const float* bg = (const float*)d_in[2];   // (8,)
    const float* We = (const float*)d_in[3];   // (8,1024,1024)
    const float* be = (const float*)d_in[4];   // (8,1024)
    float* out = (float*)d_out;                // (4,4096,1024) f32

    zero_cnt_kernel<<<1, 32>>>();
    gate_kernel<<<NT / 8, 256>>>(x, Wg, bg);

    split_transpose_We<<<dim3(DM / 32, FF / 32, NE), dim3(32, 8)>>>(We);

    cudaFuncSetAttribute(expert_gemm_tc, cudaFuncAttributeMaxDynamicSharedMemorySize, SM_TOTAL);
    expert_gemm_tc<<<dim3((NT + BM - 1) / BM, FF / BN, NE), NTHREADS, SM_TOTAL>>>(be);

    combine_kernel<<<(NT * FF / 4) / 256, 256>>>(out);
}

// round 11
// speedup vs baseline: 1.1753x; 1.0707x over previous
#include <cuda_runtime.h>
#include <cuda_fp16.h>
#include <math.h>
#include <stdint.h>

#define NT 16384      // tokens = 4 * 4096
#define DM 1024       // d_model
#define FF 1024       // d_out
#define NE 8          // experts

// GEMM tiling
#define BM 128
#define BN 256
#define BK 32
#define CHUNKS (DM / BK)      // 32
#define PAIRS (CHUNKS / 2)    // 16

// ---- device scratch (static, allocation-free) ----
__device__ int   g_cnt[NE];
__device__ int   g_list[NE][NT];        // packed: token | (slot<<16)
__device__ float g_w[2][NT];            // gate weight per slot per token
__device__ __align__(16) __half g_scr[2][NT][FF];   // per-slot expert outputs (fp16, 64 MiB)
__device__ __align__(16) __half g_xh[(size_t)NT * DM];          // fp16 x
__device__ __align__(16) __half g_wt[(size_t)NE * FF * DM];     // [e][n][k], fp16

// ======================= aux kernels =======================
__global__ void zero_cnt_kernel() {
    if (threadIdx.x < NE) g_cnt[threadIdx.x] = 0;
}

// One warp per token: 8 dots of length 1024, warp-reduce, top-2, sigmoid, scatter.
// Also emits fp16 x (x already in registers here).
__global__ void gate_kernel(const float* __restrict__ x,
                            const float* __restrict__ Wg,
                            const float* __restrict__ bg) {
    int gwarp = (blockIdx.x * blockDim.x + threadIdx.x) >> 5;
    int lane  = threadIdx.x & 31;
    if (gwarp >= NT) return;

    const float* xr = x + (size_t)gwarp * DM;
    float xv[32];
#pragma unroll
    for (int i = 0; i < 32; i++) xv[i] = xr[lane + 32 * i];

    __half* xh = g_xh + (size_t)gwarp * DM + lane;
#pragma unroll
    for (int i = 0; i < 32; i++) xh[32 * i] = __float2half_rn(xv[i]);

    float logits[NE];
#pragma unroll
    for (int e = 0; e < NE; e++) {
        const float* wg = Wg + e * DM;
        float acc = 0.f;
#pragma unroll
        for (int i = 0; i < 32; i++) acc += xv[i] * wg[lane + 32 * i];
#pragma unroll
        for (int o = 16; o > 0; o >>= 1) acc += __shfl_xor_sync(0xffffffffu, acc, o);
        logits[e] = acc + bg[e];
    }

    if (lane == 0) {
        int b0 = 0; float v0 = logits[0];
#pragma unroll
        for (int e = 1; e < NE; e++) if (logits[e] > v0) { v0 = logits[e]; b0 = e; }
        int b1 = -1; float v1 = -INFINITY;
#pragma unroll
        for (int e = 0; e < NE; e++) if (e != b0 && logits[e] > v1) { v1 = logits[e]; b1 = e; }

        g_w[0][gwarp] = 1.f / (1.f + expf(-v0));
        g_w[1][gwarp] = 1.f / (1.f + expf(-v1));

        int p0 = atomicAdd(&g_cnt[b0], 1);
        g_list[b0][p0] = gwarp;
        int p1 = atomicAdd(&g_cnt[b1], 1);
        g_list[b1][p1] = gwarp | (1 << 16);
    }
}

// We[e][k][n] -> WT[e][n][k] (transpose, fp16), 32x32 tiles.
__global__ void split_transpose_We(const float* __restrict__ We) {
    __shared__ float tile[32][33];
    int e  = blockIdx.z;
    int k0 = blockIdx.x * 32;
    int n0 = blockIdx.y * 32;
    int tx = threadIdx.x, ty = threadIdx.y;

    const float* src = We + ((size_t)e * DM) * FF;
#pragma unroll
    for (int i = ty; i < 32; i += 8)
        tile[i][tx] = src[(size_t)(k0 + i) * FF + n0 + tx];
    __syncthreads();
#pragma unroll
    for (int i = ty; i < 32; i += 8) {
        float v = tile[tx][i];  // = We[e][k0+tx][n0+i]
        size_t di = ((size_t)e * FF + (n0 + i)) * DM + k0 + tx;
        g_wt[di] = __float2half_rn(v);
    }
}

// ======================= HMMA expert GEMM =======================
// smem layout (bytes):
//   [0,512)    s_entry (128 int)
//   [512,1024) s_w     (128 float)
//   [1024, +4*30720) 4 stages; per stage: A rows 0..127 then B rows 0..255,
//   each row 80B (64B data + 16B pad)
#define ROWB 80
#define ATILEB (128 * ROWB)      // 10240
#define STAGEB (384 * ROWB)      // 30720 (A 128 rows + B 256 rows)
#define SM_TILES 1024
#define SM_TOTAL (SM_TILES + 4 * STAGEB)   // 123904

__device__ __forceinline__ uint32_t smem_u32(const void* p) {
    uint32_t a;
    asm("{ .reg .u64 t; cvta.to.shared.u64 t, %1; cvt.u32.u64 %0, t; }" : "=r"(a) : "l"(p));
    return a;
}
#define CP_ASYNC16(dst, src) \
    asm volatile("cp.async.cg.shared.global [%0], [%1], 16;" :: "r"(dst), "l"(src))
#define CP_COMMIT() asm volatile("cp.async.commit_group;")
#define CP_WAIT0()  asm volatile("cp.async.wait_group 0;")

__device__ __forceinline__ void ldsm_x4(uint32_t a, uint32_t& r0, uint32_t& r1,
                                        uint32_t& r2, uint32_t& r3) {
    asm volatile("ldmatrix.sync.aligned.m8n8.x4.shared.b16 {%0,%1,%2,%3}, [%4];"
                 : "=r"(r0), "=r"(r1), "=r"(r2), "=r"(r3) : "r"(a));
}
__device__ __forceinline__ void mma16816(float* c, uint32_t a0, uint32_t a1,
                                         uint32_t a2, uint32_t a3,
                                         uint32_t b0, uint32_t b1) {
    asm volatile(
        "mma.sync.aligned.m16n8k16.row.col.f32.f16.f16.f32 "
        "{%0,%1,%2,%3}, {%4,%5,%6,%7}, {%8,%9}, {%0,%1,%2,%3};"
        : "+f"(c[0]), "+f"(c[1]), "+f"(c[2]), "+f"(c[3])
        : "r"(a0), "r"(a1), "r"(a2), "r"(a3), "r"(b0), "r"(b1));
}

__global__ void __launch_bounds__(256) expert_gemm_tc(const float* __restrict__ be) {
    extern __shared__ char smem[];
    int e   = blockIdx.z;
    int cnt = g_cnt[e];
    int m0  = blockIdx.x * BM;
    if (m0 >= cnt) return;
    int n0  = blockIdx.y * BN;

    int tid  = threadIdx.x;
    int wid  = tid >> 5;
    int lane = tid & 31;

    int*   s_entry = (int*)smem;
    float* s_w     = (float*)(smem + 512);

    // routing metadata for this row-block
    if (tid < BM) {
        int mi = m0 + tid;
        int entry = (mi < cnt) ? g_list[e][mi] : 0;
        s_entry[tid] = entry;
        s_w[tid]     = g_w[entry >> 16][entry & 0xFFFF];
    }
    __syncthreads();

    // ---- cp.async mapping: 1536 granules of 16B per stage (384 rows x 4) ----
    const char* src6[6];
    uint32_t    dst6[6];
    uint32_t sb = smem_u32(smem);
#pragma unroll
    for (int i = 0; i < 6; i++) {
        int g   = i * 256 + tid;
        int row = g >> 2;
        int q   = g & 3;
        const __half* base;
        if (row < 128) {
            base = g_xh + (size_t)(s_entry[row] & 0xFFFF) * DM;
        } else {
            base = g_wt + ((size_t)e * FF + n0 + (row - 128)) * DM;
        }
        src6[i] = (const char*)(base + q * 8);
        dst6[i] = sb + SM_TILES + (uint32_t)(row * ROWB + q * 16);
    }

#define FILL_STAGE(stoff, kbytes) do {                                             \
        uint32_t d = (stoff);                                                      \
        CP_ASYNC16(dst6[0] + d, src6[0] + (kbytes));                               \
        CP_ASYNC16(dst6[1] + d, src6[1] + (kbytes));                               \
        CP_ASYNC16(dst6[2] + d, src6[2] + (kbytes));                               \
        CP_ASYNC16(dst6[3] + d, src6[3] + (kbytes));                               \
        CP_ASYNC16(dst6[4] + d, src6[4] + (kbytes));                               \
        CP_ASYNC16(dst6[5] + d, src6[5] + (kbytes));                               \
    } while (0)

    // ---- ldmatrix per-lane offsets ----
    uint32_t a_lane = (uint32_t)((lane & 15) * ROWB + (lane >> 4) * 16);
    uint32_t b_lane = (uint32_t)(((lane >> 4) * 8 + (lane & 7)) * ROWB + ((lane >> 3) & 1) * 16);

    int wm = wid & 1;         // 2 warps in M (64 rows each)
    int wn = wid >> 1;        // 4 warps in N (64 cols each)
    uint32_t a_warp = a_lane + (uint32_t)(wm * 64) * ROWB;
    uint32_t b_warp = b_lane + (uint32_t)(wn * 64) * ROWB + ATILEB;

    float acc[4][8][4];
#pragma unroll
    for (int i = 0; i < 4; i++)
#pragma unroll
        for (int j = 0; j < 8; j++)
#pragma unroll
            for (int k = 0; k < 4; k++) acc[i][j][k] = 0.f;

    // prologue: pair 0 (chunks 0,1 -> stages 0,1), one group
    FILL_STAGE(0, 0);
    FILL_STAGE(STAGEB, BK * 2);
    CP_COMMIT();

    for (int p = 0; p < PAIRS; ++p) {
        CP_WAIT0();                 // pair p landed (only group outstanding)
        __syncthreads();            // everyone done reading the stages we refill below
        if (p + 1 < PAIRS) {
            int c2 = 2 * (p + 1);
            FILL_STAGE((uint32_t)(c2 & 3) * STAGEB, c2 * BK * 2);
            FILL_STAGE((uint32_t)((c2 + 1) & 3) * STAGEB, (c2 + 1) * BK * 2);
            CP_COMMIT();
        }

#pragma unroll
        for (int cc = 0; cc < 2; ++cc) {
            int c = 2 * p + cc;
            uint32_t stage = sb + SM_TILES + (uint32_t)(c & 3) * STAGEB;
            uint32_t Aw = stage + a_warp;
            uint32_t Bw = stage + b_warp;

#pragma unroll
            for (int s = 0; s < 2; s++) {
                // kstep skew: even warps do ksteps 0,1; odd warps 1,0
                uint32_t kb = (uint32_t)(((s + wid) & 1) * 32);

                uint32_t a[4][4], b[4][4];
#pragma unroll
                for (int mt = 0; mt < 4; mt++)
                    ldsm_x4(Aw + (uint32_t)(mt * 16) * ROWB + kb,
                            a[mt][0], a[mt][1], a[mt][2], a[mt][3]);
#pragma unroll
                for (int n2 = 0; n2 < 4; n2++)
                    ldsm_x4(Bw + (uint32_t)(n2 * 16) * ROWB + kb,
                            b[n2][0], b[n2][1], b[n2][2], b[n2][3]);
#pragma unroll
                for (int mt = 0; mt < 4; mt++)
#pragma unroll
                    for (int n2 = 0; n2 < 4; n2++) {
                        mma16816(acc[mt][n2 * 2 + 0], a[mt][0], a[mt][1], a[mt][2], a[mt][3],
                                 b[n2][0], b[n2][1]);
                        mma16816(acc[mt][n2 * 2 + 1], a[mt][0], a[mt][1], a[mt][2], a[mt][3],
                                 b[n2][2], b[n2][3]);
                    }
            }
        }
    }

    // ---- epilogue (fp16 scratch) ----
    int qrow = lane >> 2;          // 0..7
    int qcol = (lane & 3) * 2;     // 0,2,4,6
    float2 bias2[8];
#pragma unroll
    for (int nt = 0; nt < 8; nt++) {
        int nc = n0 + wn * 64 + nt * 8 + qcol;
        bias2[nt] = make_float2(be[e * FF + nc], be[e * FF + nc + 1]);
    }
#pragma unroll
    for (int mt = 0; mt < 4; mt++) {
#pragma unroll
        for (int half = 0; half < 2; half++) {
            int mrow = wm * 64 + mt * 16 + half * 8 + qrow;
            if (m0 + mrow < cnt) {
                int entry = s_entry[mrow];
                int tok   = entry & 0xFFFF;
                int slot  = entry >> 16;
                float w   = s_w[mrow];
#pragma unroll
                for (int nt = 0; nt < 8; nt++) {
                    int nc = n0 + wn * 64 + nt * 8 + qcol;
                    float ox = (acc[mt][nt][half * 2 + 0] + bias2[nt].x) * w;
                    float oy = (acc[mt][nt][half * 2 + 1] + bias2[nt].y) * w;
                    *(__half2*)&g_scr[slot][tok][nc] = __floats2half2_rn(ox, oy);
                }
            }
        }
    }
}

// out = scr[0] + scr[1]  (fp16 -> fp32)
__global__ void combine_kernel(float* __restrict__ out) {
    size_t j = (size_t)blockIdx.x * blockDim.x + threadIdx.x;  // one float4 (4 elems)
    const uint2* a = (const uint2*)g_scr[0];   // 4 halves
    const uint2* b = (const uint2*)g_scr[1];
    uint2 ua = a[j], ub = b[j];
    float2 a0 = __half22float2(*(__half2*)&ua.x);
    float2 a1 = __half22float2(*(__half2*)&ua.y);
    float2 b0 = __half22float2(*(__half2*)&ub.x);
    float2 b1 = __half22float2(*(__half2*)&ub.y);
    ((float4*)out)[j] = make_float4(a0.x + b0.x, a0.y + b0.y, a1.x + b1.x, a1.y + b1.y);
}

extern "C" void kernel_launch(void* const* d_in, const int* in_sizes, int n_in,
                              void* d_out, int out_size) {
    const float* x  = (const float*)d_in[0];   // (4,4096,1024)
    const float* Wg = (const float*)d_in[1];   // (8,1024)
    const float* bg = (const float*)d_in[2];   // (8,)
    const float* We = (const float*)d_in[3];   // (8,1024,1024)
    const float* be = (const float*)d_in[4];   // (8,1024)
    float* out = (float*)d_out;                // (4,4096,1024) f32

    zero_cnt_kernel<<<1, 32>>>();
    gate_kernel<<<NT / 8, 256>>>(x, Wg, bg);

    split_transpose_We<<<dim3(DM / 32, FF / 32, NE), dim3(32, 8)>>>(We);

    cudaFuncSetAttribute(expert_gemm_tc, cudaFuncAttributeMaxDynamicSharedMemorySize, SM_TOTAL);
    expert_gemm_tc<<<dim3(NT / BM, FF / BN, NE), 256, SM_TOTAL>>>(be);

    combine_kernel<<<(NT * FF / 4) / 256, 256>>>(out);
}

// round 13
// speedup vs baseline: 1.1999x; 1.0209x over previous
#include <cuda_runtime.h>
#include <cuda_fp16.h>
#include <math.h>
#include <stdint.h>

#define NT 16384      // tokens = 4 * 4096
#define DM 1024       // d_model
#define FF 1024       // d_out
#define NE 8          // experts

// GEMM tiling
#define BM 128
#define BN 256
#define BK 32
#define CHUNKS (DM / BK)      // 32
#define PAIRS (CHUNKS / 2)    // 16

// ---- device scratch (static, allocation-free) ----
__device__ int   g_cnt[NE];
__device__ int   g_list[NE][NT];        // packed: token | (slot<<16)
__device__ float g_w[2][NT];            // gate weight per slot per token
__device__ __align__(16) __half g_scr[2][NT][FF];   // per-slot expert outputs (fp16, 64 MiB)
__device__ __align__(16) __half g_xh[(size_t)NT * DM];          // fp16 x
__device__ __align__(16) __half g_wt[(size_t)NE * FF * DM];     // [e][n][k], fp16

// ======================= aux kernels =======================
__global__ void zero_cnt_kernel() {
    if (threadIdx.x < NE) g_cnt[threadIdx.x] = 0;
}

// One warp per token: 8 dots of length 1024, warp-reduce, top-2, sigmoid, scatter.
// Also emits fp16 x (x already in registers here).
__global__ void gate_kernel(const float* __restrict__ x,
                            const float* __restrict__ Wg,
                            const float* __restrict__ bg) {
    int gwarp = (blockIdx.x * blockDim.x + threadIdx.x) >> 5;
    int lane  = threadIdx.x & 31;
    if (gwarp >= NT) return;

    const float* xr = x + (size_t)gwarp * DM;
    float xv[32];
#pragma unroll
    for (int i = 0; i < 32; i++) xv[i] = xr[lane + 32 * i];

    __half* xh = g_xh + (size_t)gwarp * DM + lane;
#pragma unroll
    for (int i = 0; i < 32; i++) xh[32 * i] = __float2half_rn(xv[i]);

    float logits[NE];
#pragma unroll
    for (int e = 0; e < NE; e++) {
        const float* wg = Wg + e * DM;
        float acc = 0.f;
#pragma unroll
        for (int i = 0; i < 32; i++) acc += xv[i] * wg[lane + 32 * i];
#pragma unroll
        for (int o = 16; o > 0; o >>= 1) acc += __shfl_xor_sync(0xffffffffu, acc, o);
        logits[e] = acc + bg[e];
    }

    if (lane == 0) {
        int b0 = 0; float v0 = logits[0];
#pragma unroll
        for (int e = 1; e < NE; e++) if (logits[e] > v0) { v0 = logits[e]; b0 = e; }
        int b1 = -1; float v1 = -INFINITY;
#pragma unroll
        for (int e = 0; e < NE; e++) if (e != b0 && logits[e] > v1) { v1 = logits[e]; b1 = e; }

        g_w[0][gwarp] = 1.f / (1.f + expf(-v0));
        g_w[1][gwarp] = 1.f / (1.f + expf(-v1));

        int p0 = atomicAdd(&g_cnt[b0], 1);
        g_list[b0][p0] = gwarp;
        int p1 = atomicAdd(&g_cnt[b1], 1);
        g_list[b1][p1] = gwarp | (1 << 16);
    }
}

// We[e][k][n] -> WT[e][n][k] (transpose, fp16), 32x32 tiles.
__global__ void split_transpose_We(const float* __restrict__ We) {
    __shared__ float tile[32][33];
    int e  = blockIdx.z;
    int k0 = blockIdx.x * 32;
    int n0 = blockIdx.y * 32;
    int tx = threadIdx.x, ty = threadIdx.y;

    const float* src = We + ((size_t)e * DM) * FF;
#pragma unroll
    for (int i = ty; i < 32; i += 8)
        tile[i][tx] = src[(size_t)(k0 + i) * FF + n0 + tx];
    __syncthreads();
#pragma unroll
    for (int i = ty; i < 32; i += 8) {
        float v = tile[tx][i];  // = We[e][k0+tx][n0+i]
        size_t di = ((size_t)e * FF + (n0 + i)) * DM + k0 + tx;
        g_wt[di] = __float2half_rn(v);
    }
}

// ======================= HMMA expert GEMM =======================
// smem layout (bytes):
//   [0,512)    s_entry (128 int)
//   [512,1024) s_w     (128 float)
//   [1024, +4*30720) 4 stages; per stage: A rows 0..127 then B rows 0..255,
//   each row 80B (64B data + 16B pad)
#define ROWB 80
#define ATILEB (128 * ROWB)      // 10240
#define STAGEB (384 * ROWB)      // 30720 (A 128 rows + B 256 rows)
#define SM_TILES 1024
#define SM_TOTAL (SM_TILES + 4 * STAGEB)   // 123904

__device__ __forceinline__ uint32_t smem_u32(const void* p) {
    uint32_t a;
    asm("{ .reg .u64 t; cvta.to.shared.u64 t, %1; cvt.u32.u64 %0, t; }" : "=r"(a) : "l"(p));
    return a;
}
#define CP_ASYNC16(dst, src) \
    asm volatile("cp.async.cg.shared.global [%0], [%1], 16;" :: "r"(dst), "l"(src))
#define CP_COMMIT() asm volatile("cp.async.commit_group;")
#define CP_WAIT0()  asm volatile("cp.async.wait_group 0;")

__device__ __forceinline__ void ldsm_x4(uint32_t a, uint32_t& r0, uint32_t& r1,
                                        uint32_t& r2, uint32_t& r3) {
    asm volatile("ldmatrix.sync.aligned.m8n8.x4.shared.b16 {%0,%1,%2,%3}, [%4];"
                 : "=r"(r0), "=r"(r1), "=r"(r2), "=r"(r3) : "r"(a));
}
__device__ __forceinline__ void mma16816(float* c, uint32_t a0, uint32_t a1,
                                         uint32_t a2, uint32_t a3,
                                         uint32_t b0, uint32_t b1) {
    asm volatile(
        "mma.sync.aligned.m16n8k16.row.col.f32.f16.f16.f32 "
        "{%0,%1,%2,%3}, {%4,%5,%6,%7}, {%8,%9}, {%0,%1,%2,%3};"
        : "+f"(c[0]), "+f"(c[1]), "+f"(c[2]), "+f"(c[3])
        : "r"(a0), "r"(a1), "r"(a2), "r"(a3), "r"(b0), "r"(b1));
}

__global__ void __launch_bounds__(256) expert_gemm_tc(const float* __restrict__ be) {
    extern __shared__ char smem[];
    int e   = blockIdx.z;
    int cnt = g_cnt[e];
    int m0  = blockIdx.x * BM;
    if (m0 >= cnt) return;
    int n0  = blockIdx.y * BN;

    int tid  = threadIdx.x;
    int wid  = tid >> 5;
    int lane = tid & 31;

    int*   s_entry = (int*)smem;
    float* s_w     = (float*)(smem + 512);

    // routing metadata for this row-block
    if (tid < BM) {
        int mi = m0 + tid;
        int entry = (mi < cnt) ? g_list[e][mi] : 0;
        s_entry[tid] = entry;
        s_w[tid]     = g_w[entry >> 16][entry & 0xFFFF];
    }
    __syncthreads();

    // ---- cp.async mapping: 1536 granules of 16B per stage (384 rows x 4) ----
    const char* src6[6];
    uint32_t    dst6[6];
    uint32_t sb = smem_u32(smem);
#pragma unroll
    for (int i = 0; i < 6; i++) {
        int g   = i * 256 + tid;
        int row = g >> 2;
        int q   = g & 3;
        const __half* base;
        if (row < 128) {
            base = g_xh + (size_t)(s_entry[row] & 0xFFFF) * DM;
        } else {
            base = g_wt + ((size_t)e * FF + n0 + (row - 128)) * DM;
        }
        src6[i] = (const char*)(base + q * 8);
        dst6[i] = sb + SM_TILES + (uint32_t)(row * ROWB + q * 16);
    }

#define FILL_STAGE(stoff, kbytes) do {                                             \
        uint32_t d = (stoff);                                                      \
        CP_ASYNC16(dst6[0] + d, src6[0] + (kbytes));                               \
        CP_ASYNC16(dst6[1] + d, src6[1] + (kbytes));                               \
        CP_ASYNC16(dst6[2] + d, src6[2] + (kbytes));                               \
        CP_ASYNC16(dst6[3] + d, src6[3] + (kbytes));                               \
        CP_ASYNC16(dst6[4] + d, src6[4] + (kbytes));                               \
        CP_ASYNC16(dst6[5] + d, src6[5] + (kbytes));                               \
    } while (0)

    // ---- ldmatrix per-lane offsets ----
    uint32_t a_lane = (uint32_t)((lane & 15) * ROWB + (lane >> 4) * 16);
    uint32_t b_lane = (uint32_t)(((lane >> 4) * 8 + (lane & 7)) * ROWB + ((lane >> 3) & 1) * 16);

    int wm = wid & 1;         // 2 warps in M (64 rows each)
    int wn = wid >> 1;        // 4 warps in N (64 cols each)
    uint32_t a_warp = a_lane + (uint32_t)(wm * 64) * ROWB;
    uint32_t b_warp = b_lane + (uint32_t)(wn * 64) * ROWB + ATILEB;

    float acc[4][8][4];
#pragma unroll
    for (int i = 0; i < 4; i++)
#pragma unroll
        for (int j = 0; j < 8; j++)
#pragma unroll
            for (int k = 0; k < 4; k++) acc[i][j][k] = 0.f;

    // fragments: single A buffer, double B buffer
    uint32_t a[4][4], b[2][4][4];

#define LOAD_A(Aw, kb) do {                                                        \
        _Pragma("unroll")                                                          \
        for (int mt = 0; mt < 4; mt++)                                             \
            ldsm_x4((Aw) + (uint32_t)(mt * 16) * ROWB + (kb),                      \
                    a[mt][0], a[mt][1], a[mt][2], a[mt][3]);                       \
    } while (0)
#define LOAD_B(buf, Bw, kb) do {                                                   \
        _Pragma("unroll")                                                          \
        for (int n2 = 0; n2 < 4; n2++)                                             \
            ldsm_x4((Bw) + (uint32_t)(n2 * 16) * ROWB + (kb),                      \
                    b[buf][n2][0], b[buf][n2][1], b[buf][n2][2], b[buf][n2][3]);   \
    } while (0)
#define DO_MMAS(buf) do {                                                          \
        _Pragma("unroll")                                                          \
        for (int mt = 0; mt < 4; mt++)                                             \
            _Pragma("unroll")                                                      \
            for (int n2 = 0; n2 < 4; n2++) {                                       \
                mma16816(acc[mt][n2 * 2 + 0],                                      \
                         a[mt][0], a[mt][1], a[mt][2], a[mt][3],                   \
                         b[buf][n2][0], b[buf][n2][1]);                            \
                mma16816(acc[mt][n2 * 2 + 1],                                      \
                         a[mt][0], a[mt][1], a[mt][2], a[mt][3],                   \
                         b[buf][n2][2], b[buf][n2][3]);                            \
            }                                                                      \
    } while (0)

    // prologue: pair 0 (chunks 0,1 -> stages 0,1), one group
    FILL_STAGE(0, 0);
    FILL_STAGE(STAGEB, BK * 2);
    CP_COMMIT();

    for (int p = 0; p < PAIRS; ++p) {
        CP_WAIT0();                 // pair p landed (only group outstanding)
        __syncthreads();            // everyone done reading the stages refilled below
        if (p + 1 < PAIRS) {
            int c2 = 2 * (p + 1);
            FILL_STAGE((uint32_t)(c2 & 3) * STAGEB, c2 * BK * 2);
            FILL_STAGE((uint32_t)((c2 + 1) & 3) * STAGEB, (c2 + 1) * BK * 2);
            CP_COMMIT();
        }

        int c0 = 2 * p;
        uint32_t st0 = sb + SM_TILES + (uint32_t)(c0 & 3) * STAGEB;
        uint32_t st1 = sb + SM_TILES + (uint32_t)((c0 + 1) & 3) * STAGEB;
        uint32_t Aw0 = st0 + a_warp, Bw0 = st0 + b_warp;
        uint32_t Aw1 = st1 + a_warp, Bw1 = st1 + b_warp;

        // software-pipelined pair: only the first load group is latency-exposed
        LOAD_A(Aw0, 0u);
        LOAD_B(0, Bw0, 0u);
        LOAD_B(1, Bw0, 32u);
        DO_MMAS(0);                 // (A c0k0, B c0k0)
        LOAD_A(Aw0, 32u);           // A c0k1 (WAR on a: MMAs above already read)
        LOAD_B(0, Bw1, 0u);         // B c1k0 into freed buf0
        DO_MMAS(1);                 // (A c0k1, B c0k1)
        LOAD_A(Aw1, 0u);            // A c1k0
        LOAD_B(1, Bw1, 32u);        // B c1k1
        DO_MMAS(0);                 // (A c1k0, B c1k0)
        LOAD_A(Aw1, 32u);           // A c1k1
        DO_MMAS(1);                 // (A c1k1, B c1k1)
    }

    // ---- epilogue (fp16 scratch) ----
    int qrow = lane >> 2;          // 0..7
    int qcol = (lane & 3) * 2;     // 0,2,4,6
    float2 bias2[8];
#pragma unroll
    for (int nt = 0; nt < 8; nt++) {
        int nc = n0 + wn * 64 + nt * 8 + qcol;
        bias2[nt] = make_float2(be[e * FF + nc], be[e * FF + nc + 1]);
    }
#pragma unroll
    for (int mt = 0; mt < 4; mt++) {
#pragma unroll
        for (int half = 0; half < 2; half++) {
            int mrow = wm * 64 + mt * 16 + half * 8 + qrow;
            if (m0 + mrow < cnt) {
                int entry = s_entry[mrow];
                int tok   = entry & 0xFFFF;
                int slot  = entry >> 16;
                float w   = s_w[mrow];
#pragma unroll
                for (int nt = 0; nt < 8; nt++) {
                    int nc = n0 + wn * 64 + nt * 8 + qcol;
                    float ox = (acc[mt][nt][half * 2 + 0] + bias2[nt].x) * w;
                    float oy = (acc[mt][nt][half * 2 + 1] + bias2[nt].y) * w;
                    *(__half2*)&g_scr[slot][tok][nc] = __floats2half2_rn(ox, oy);
                }
            }
        }
    }
}

// out = scr[0] + scr[1]  (fp16 -> fp32)
__global__ void combine_kernel(float* __restrict__ out) {
    size_t j = (size_t)blockIdx.x * blockDim.x + threadIdx.x;  // one float4 (4 elems)
    const uint2* a = (const uint2*)g_scr[0];   // 4 halves
    const uint2* b = (const uint2*)g_scr[1];
    uint2 ua = a[j], ub = b[j];
    float2 a0 = __half22float2(*(__half2*)&ua.x);
    float2 a1 = __half22float2(*(__half2*)&ua.y);
    float2 b0 = __half22float2(*(__half2*)&ub.x);
    float2 b1 = __half22float2(*(__half2*)&ub.y);
    ((float4*)out)[j] = make_float4(a0.x + b0.x, a0.y + b0.y, a1.x + b1.x, a1.y + b1.y);
}

extern "C" void kernel_launch(void* const* d_in, const int* in_sizes, int n_in,
                              void* d_out, int out_size) {
    const float* x  = (const float*)d_in[0];   // (4,4096,1024)
    const float* Wg = (const float*)d_in[1];   // (8,1024)
    const float* bg = (const float*)d_in[2];   // (8,)
    const float* We = (const float*)d_in[3];   // (8,1024,1024)
    const float* be = (const float*)d_in[4];   // (8,1024)
    float* out = (float*)d_out;                // (4,4096,1024) f32

    zero_cnt_kernel<<<1, 32>>>();
    gate_kernel<<<NT / 8, 256>>>(x, Wg, bg);

    split_transpose_We<<<dim3(DM / 32, FF / 32, NE), dim3(32, 8)>>>(We);

    cudaFuncSetAttribute(expert_gemm_tc, cudaFuncAttributeMaxDynamicSharedMemorySize, SM_TOTAL);
    expert_gemm_tc<<<dim3(NT / BM, FF / BN, NE), 256, SM_TOTAL>>>(be);

    combine_kernel<<<(NT * FF / 4) / 256, 256>>>(out);
}

// round 14
// speedup vs baseline: 1.2245x; 1.0206x over previous
#include <cuda_runtime.h>
#include <cuda_fp16.h>
#include <math.h>
#include <stdint.h>

#define NT 16384      // tokens = 4 * 4096
#define DM 1024       // d_model
#define FF 1024       // d_out
#define NE 8          // experts

// GEMM tiling
#define BM 128
#define BN 256
#define BK 32
#define CHUNKS (DM / BK)      // 32
#define PAIRS (CHUNKS / 2)    // 16

// ---- device scratch (static, allocation-free) ----
__device__ int   g_cnt[NE];
__device__ int   g_list[NE][NT];        // packed: token | (slot<<16)
__device__ float g_w[2][NT];            // gate weight per slot per token
__device__ __align__(16) __half g_scr[2][NT][FF];   // per-slot expert outputs (fp16, 64 MiB)
__device__ __align__(16) __half g_xh[(size_t)NT * DM];          // fp16 x
__device__ __align__(16) __half g_wt[(size_t)NE * FF * DM];     // [e][n][k], fp16

// ======================= aux kernels =======================
__global__ void zero_cnt_kernel() {
    if (threadIdx.x < NE) g_cnt[threadIdx.x] = 0;
}

// One warp per token: 8 dots of length 1024, warp-reduce, top-2, sigmoid, scatter.
// Also emits fp16 x (x already in registers here).
__global__ void gate_kernel(const float* __restrict__ x,
                            const float* __restrict__ Wg,
                            const float* __restrict__ bg) {
    int gwarp = (blockIdx.x * blockDim.x + threadIdx.x) >> 5;
    int lane  = threadIdx.x & 31;
    if (gwarp >= NT) return;

    const float* xr = x + (size_t)gwarp * DM;
    float xv[32];
#pragma unroll
    for (int i = 0; i < 32; i++) xv[i] = xr[lane + 32 * i];

    __half* xh = g_xh + (size_t)gwarp * DM + lane;
#pragma unroll
    for (int i = 0; i < 32; i++) xh[32 * i] = __float2half_rn(xv[i]);

    float logits[NE];
#pragma unroll
    for (int e = 0; e < NE; e++) {
        const float* wg = Wg + e * DM;
        float acc = 0.f;
#pragma unroll
        for (int i = 0; i < 32; i++) acc += xv[i] * wg[lane + 32 * i];
#pragma unroll
        for (int o = 16; o > 0; o >>= 1) acc += __shfl_xor_sync(0xffffffffu, acc, o);
        logits[e] = acc + bg[e];
    }

    if (lane == 0) {
        int b0 = 0; float v0 = logits[0];
#pragma unroll
        for (int e = 1; e < NE; e++) if (logits[e] > v0) { v0 = logits[e]; b0 = e; }
        int b1 = -1; float v1 = -INFINITY;
#pragma unroll
        for (int e = 0; e < NE; e++) if (e != b0 && logits[e] > v1) { v1 = logits[e]; b1 = e; }

        g_w[0][gwarp] = 1.f / (1.f + expf(-v0));
        g_w[1][gwarp] = 1.f / (1.f + expf(-v1));

        int p0 = atomicAdd(&g_cnt[b0], 1);
        g_list[b0][p0] = gwarp;
        int p1 = atomicAdd(&g_cnt[b1], 1);
        g_list[b1][p1] = gwarp | (1 << 16);
    }
}

// We[e][k][n] -> WT[e][n][k] (transpose, fp16), 64x64 tiles, vectorized both sides.
__global__ void __launch_bounds__(256) split_transpose_We(const float* __restrict__ We) {
    __shared__ float tile[64][65];
    int e  = blockIdx.z;
    int k0 = blockIdx.x * 64;
    int n0 = blockIdx.y * 64;
    int tid = threadIdx.x;

    const float* src = We + (size_t)e * DM * FF;
    // load 64x64 floats: float4 per thread, 16 rows per pass x 4 passes
    int r  = tid >> 4;        // 0..15
    int c4 = tid & 15;        // 16 float4 = 64 floats per row
#pragma unroll
    for (int rr = 0; rr < 64; rr += 16) {
        float4 v = *(const float4*)&src[(size_t)(k0 + rr + r) * FF + n0 + c4 * 4];
        tile[rr + r][c4 * 4 + 0] = v.x;
        tile[rr + r][c4 * 4 + 1] = v.y;
        tile[rr + r][c4 * 4 + 2] = v.z;
        tile[rr + r][c4 * 4 + 3] = v.w;
    }
    __syncthreads();

    // store: thread -> n row (tid&63), k segment of 16 ((tid>>6)*16); 16 halves = 2x16B
    int nl = tid & 63;
    int ks = (tid >> 6) * 16;
    __half hbuf[16];
#pragma unroll
    for (int i = 0; i < 16; i++) hbuf[i] = __float2half_rn(tile[ks + i][nl]);
    __half* dst = g_wt + ((size_t)e * FF + n0 + nl) * DM + k0 + ks;
    *(uint4*)(dst + 0) = *(uint4*)(hbuf + 0);
    *(uint4*)(dst + 8) = *(uint4*)(hbuf + 8);
}

// ======================= HMMA expert GEMM =======================
// smem layout (bytes):
//   [0,512)    s_entry (128 int)
//   [512,1024) s_w     (128 float)
//   [1024, +6*30720) 6 chunk-stages; per stage: A rows 0..127 then B rows 0..255,
//   each row 80B (64B data + 16B pad)
#define ROWB 80
#define ATILEB (128 * ROWB)      // 10240
#define STAGEB (384 * ROWB)      // 30720 (A 128 rows + B 256 rows)
#define NSTG 6
#define SM_TILES 1024
#define SM_TOTAL (SM_TILES + NSTG * STAGEB)   // 185344

__device__ __forceinline__ uint32_t smem_u32(const void* p) {
    uint32_t a;
    asm("{ .reg .u64 t; cvta.to.shared.u64 t, %1; cvt.u32.u64 %0, t; }" : "=r"(a) : "l"(p));
    return a;
}
#define CP_ASYNC16(dst, src) \
    asm volatile("cp.async.cg.shared.global [%0], [%1], 16;" :: "r"(dst), "l"(src))
#define CP_COMMIT() asm volatile("cp.async.commit_group;")
#define CP_WAIT1()  asm volatile("cp.async.wait_group 1;")
#define CP_WAIT0()  asm volatile("cp.async.wait_group 0;")

__device__ __forceinline__ void ldsm_x4(uint32_t a, uint32_t& r0, uint32_t& r1,
                                        uint32_t& r2, uint32_t& r3) {
    asm volatile("ldmatrix.sync.aligned.m8n8.x4.shared.b16 {%0,%1,%2,%3}, [%4];"
                 : "=r"(r0), "=r"(r1), "=r"(r2), "=r"(r3) : "r"(a));
}
__device__ __forceinline__ void mma16816(float* c, uint32_t a0, uint32_t a1,
                                         uint32_t a2, uint32_t a3,
                                         uint32_t b0, uint32_t b1) {
    asm volatile(
        "mma.sync.aligned.m16n8k16.row.col.f32.f16.f16.f32 "
        "{%0,%1,%2,%3}, {%4,%5,%6,%7}, {%8,%9}, {%0,%1,%2,%3};"
        : "+f"(c[0]), "+f"(c[1]), "+f"(c[2]), "+f"(c[3])
        : "r"(a0), "r"(a1), "r"(a2), "r"(a3), "r"(b0), "r"(b1));
}

__global__ void __launch_bounds__(256) expert_gemm_tc(const float* __restrict__ be) {
    extern __shared__ char smem[];
    int e   = blockIdx.z;
    int cnt = g_cnt[e];
    int m0  = blockIdx.x * BM;
    if (m0 >= cnt) return;
    int n0  = blockIdx.y * BN;

    int tid  = threadIdx.x;
    int wid  = tid >> 5;
    int lane = tid & 31;

    int*   s_entry = (int*)smem;
    float* s_w     = (float*)(smem + 512);

    // routing metadata for this row-block
    if (tid < BM) {
        int mi = m0 + tid;
        int entry = (mi < cnt) ? g_list[e][mi] : 0;
        s_entry[tid] = entry;
        s_w[tid]     = g_w[entry >> 16][entry & 0xFFFF];
    }
    __syncthreads();

    // ---- cp.async mapping: 1536 granules of 16B per stage (384 rows x 4) ----
    const char* src6[6];
    uint32_t    dst6[6];
    uint32_t sb = smem_u32(smem);
#pragma unroll
    for (int i = 0; i < 6; i++) {
        int g   = i * 256 + tid;
        int row = g >> 2;
        int q   = g & 3;
        const __half* base;
        if (row < 128) {
            base = g_xh + (size_t)(s_entry[row] & 0xFFFF) * DM;
        } else {
            base = g_wt + ((size_t)e * FF + n0 + (row - 128)) * DM;
        }
        src6[i] = (const char*)(base + q * 8);
        dst6[i] = sb + SM_TILES + (uint32_t)(row * ROWB + q * 16);
    }

#define FILL_STAGE(stoff, kbytes) do {                                             \
        uint32_t d = (stoff);                                                      \
        CP_ASYNC16(dst6[0] + d, src6[0] + (kbytes));                               \
        CP_ASYNC16(dst6[1] + d, src6[1] + (kbytes));                               \
        CP_ASYNC16(dst6[2] + d, src6[2] + (kbytes));                               \
        CP_ASYNC16(dst6[3] + d, src6[3] + (kbytes));                               \
        CP_ASYNC16(dst6[4] + d, src6[4] + (kbytes));                               \
        CP_ASYNC16(dst6[5] + d, src6[5] + (kbytes));                               \
    } while (0)

    // ---- ldmatrix per-lane offsets ----
    uint32_t a_lane = (uint32_t)((lane & 15) * ROWB + (lane >> 4) * 16);
    uint32_t b_lane = (uint32_t)(((lane >> 4) * 8 + (lane & 7)) * ROWB + ((lane >> 3) & 1) * 16);

    int wm = wid & 1;         // 2 warps in M (64 rows each)
    int wn = wid >> 1;        // 4 warps in N (64 cols each)
    uint32_t a_warp = a_lane + (uint32_t)(wm * 64) * ROWB;
    uint32_t b_warp = b_lane + (uint32_t)(wn * 64) * ROWB + ATILEB;

    float acc[4][8][4];
#pragma unroll
    for (int i = 0; i < 4; i++)
#pragma unroll
        for (int j = 0; j < 8; j++)
#pragma unroll
            for (int k = 0; k < 4; k++) acc[i][j][k] = 0.f;

    // fragments: single A buffer, double B buffer
    uint32_t a[4][4], b[2][4][4];

#define LOAD_A(Aw, kb) do {                                                        \
        _Pragma("unroll")                                                          \
        for (int mt = 0; mt < 4; mt++)                                             \
            ldsm_x4((Aw) + (uint32_t)(mt * 16) * ROWB + (kb),                      \
                    a[mt][0], a[mt][1], a[mt][2], a[mt][3]);                       \
    } while (0)
#define LOAD_B(buf, Bw, kb) do {                                                   \
        _Pragma("unroll")                                                          \
        for (int n2 = 0; n2 < 4; n2++)                                             \
            ldsm_x4((Bw) + (uint32_t)(n2 * 16) * ROWB + (kb),                      \
                    b[buf][n2][0], b[buf][n2][1], b[buf][n2][2], b[buf][n2][3]);   \
    } while (0)
#define DO_MMAS(buf) do {                                                          \
        _Pragma("unroll")                                                          \
        for (int mt = 0; mt < 4; mt++)                                             \
            _Pragma("unroll")                                                      \
            for (int n2 = 0; n2 < 4; n2++) {                                       \
                mma16816(acc[mt][n2 * 2 + 0],                                      \
                         a[mt][0], a[mt][1], a[mt][2], a[mt][3],                   \
                         b[buf][n2][0], b[buf][n2][1]);                            \
                mma16816(acc[mt][n2 * 2 + 1],                                      \
                         a[mt][0], a[mt][1], a[mt][2], a[mt][3],                   \
                         b[buf][n2][2], b[buf][n2][3]);                            \
            }                                                                      \
    } while (0)

    // prologue: pairs 0 and 1 in flight (2 groups)
    FILL_STAGE(0, 0);
    FILL_STAGE(STAGEB, BK * 2);
    CP_COMMIT();
    FILL_STAGE(2 * STAGEB, 2 * BK * 2);
    FILL_STAGE(3 * STAGEB, 3 * BK * 2);
    CP_COMMIT();

    for (int p = 0; p < PAIRS; ++p) {
        // outstanding groups: {p} ∪ {p+1 if exists}; pair p must be complete
        if (p + 1 < PAIRS) { CP_WAIT1(); } else { CP_WAIT0(); }
        __syncthreads();            // visibility + all warps done with pair p-1
        if (p + 2 < PAIRS) {
            int c2 = 2 * (p + 2);
            // targets stages ((2p+4)%6, (2p+5)%6) — last read in pair p-1, done above
            FILL_STAGE((uint32_t)(c2 % NSTG) * STAGEB, c2 * BK * 2);
            FILL_STAGE((uint32_t)((c2 + 1) % NSTG) * STAGEB, (c2 + 1) * BK * 2);
            CP_COMMIT();
        }

        int c0 = 2 * p;
        uint32_t st0 = sb + SM_TILES + (uint32_t)(c0 % NSTG) * STAGEB;
        uint32_t st1 = sb + SM_TILES + (uint32_t)((c0 + 1) % NSTG) * STAGEB;
        uint32_t Aw0 = st0 + a_warp, Bw0 = st0 + b_warp;
        uint32_t Aw1 = st1 + a_warp, Bw1 = st1 + b_warp;

        // software-pipelined pair: only the first load group is latency-exposed
        LOAD_A(Aw0, 0u);
        LOAD_B(0, Bw0, 0u);
        LOAD_B(1, Bw0, 32u);
        DO_MMAS(0);                 // (A c0k0, B c0k0)
        LOAD_A(Aw0, 32u);           // A c0k1
        LOAD_B(0, Bw1, 0u);         // B c1k0 into freed buf0
        DO_MMAS(1);                 // (A c0k1, B c0k1)
        LOAD_A(Aw1, 0u);            // A c1k0
        LOAD_B(1, Bw1, 32u);        // B c1k1
        DO_MMAS(0);                 // (A c1k0, B c1k0)
        LOAD_A(Aw1, 32u);           // A c1k1
        DO_MMAS(1);                 // (A c1k1, B c1k1)
    }

    // ---- epilogue (fp16 scratch) ----
    int qrow = lane >> 2;          // 0..7
    int qcol = (lane & 3) * 2;     // 0,2,4,6
    float2 bias2[8];
#pragma unroll
    for (int nt = 0; nt < 8; nt++) {
        int nc = n0 + wn * 64 + nt * 8 + qcol;
        bias2[nt] = make_float2(be[e * FF + nc], be[e * FF + nc + 1]);
    }
#pragma unroll
    for (int mt = 0; mt < 4; mt++) {
#pragma unroll
        for (int half = 0; half < 2; half++) {
            int mrow = wm * 64 + mt * 16 + half * 8 + qrow;
            if (m0 + mrow < cnt) {
                int entry = s_entry[mrow];
                int tok   = entry & 0xFFFF;
                int slot  = entry >> 16;
                float w   = s_w[mrow];
#pragma unroll
                for (int nt = 0; nt < 8; nt++) {
                    int nc = n0 + wn * 64 + nt * 8 + qcol;
                    float ox = (acc[mt][nt][half * 2 + 0] + bias2[nt].x) * w;
                    float oy = (acc[mt][nt][half * 2 + 1] + bias2[nt].y) * w;
                    *(__half2*)&g_scr[slot][tok][nc] = __floats2half2_rn(ox, oy);
                }
            }
        }
    }
}

// out = scr[0] + scr[1]  (fp16 -> fp32), 8 elements per thread
__global__ void combine_kernel(float* __restrict__ out) {
    size_t j = (size_t)blockIdx.x * blockDim.x + threadIdx.x;  // one uint4 = 8 halves
    uint4 ua = ((const uint4*)g_scr[0])[j];
    uint4 ub = ((const uint4*)g_scr[1])[j];
    float2 a0 = __half22float2(*(__half2*)&ua.x);
    float2 a1 = __half22float2(*(__half2*)&ua.y);
    float2 a2 = __half22float2(*(__half2*)&ua.z);
    float2 a3 = __half22float2(*(__half2*)&ua.w);
    float2 b0 = __half22float2(*(__half2*)&ub.x);
    float2 b1 = __half22float2(*(__half2*)&ub.y);
    float2 b2 = __half22float2(*(__half2*)&ub.z);
    float2 b3 = __half22float2(*(__half2*)&ub.w);
    float4* o = (float4*)out + 2 * j;
    o[0] = make_float4(a0.x + b0.x, a0.y + b0.y, a1.x + b1.x, a1.y + b1.y);
    o[1] = make_float4(a2.x + b2.x, a2.y + b2.y, a3.x + b3.x, a3.y + b3.y);
}

extern "C" void kernel_launch(void* const* d_in, const int* in_sizes, int n_in,
                              void* d_out, int out_size) {
    const float* x  = (const float*)d_in[0];   // (4,4096,1024)
    const float* Wg = (const float*)d_in[1];   // (8,1024)
    const float* bg = (const float*)d_in[2];   // (8,)
    const float* We = (const float*)d_in[3];   // (8,1024,1024)
    const float* be = (const float*)d_in[4];   // (8,1024)
    float* out = (float*)d_out;                // (4,4096,1024) f32

    zero_cnt_kernel<<<1, 32>>>();
    gate_kernel<<<NT / 8, 256>>>(x, Wg, bg);

    split_transpose_We<<<dim3(DM / 64, FF / 64, NE), 256>>>(We);

    cudaFuncSetAttribute(expert_gemm_tc, cudaFuncAttributeMaxDynamicSharedMemorySize, SM_TOTAL);
    expert_gemm_tc<<<dim3(NT / BM, FF / BN, NE), 256, SM_TOTAL>>>(be);

    combine_kernel<<<(NT * FF / 8) / 256, 256>>>(out);
}

// round 15
// speedup vs baseline: 1.2318x; 1.0059x over previous
#include <cuda_runtime.h>
#include <cuda_fp16.h>
#include <math.h>
#include <stdint.h>

#define NT 16384      // tokens = 4 * 4096
#define DM 1024       // d_model
#define FF 1024       // d_out
#define NE 8          // experts

// GEMM tiling
#define BM 128
#define BN 256
#define BK 32
#define CHUNKS (DM / BK)      // 32
#define PAIRS (CHUNKS / 2)    // 16

// ---- device scratch (static, allocation-free) ----
__device__ int   g_cnt[NE];
__device__ int   g_list[NE][NT];        // packed: token | (slot<<16)
__device__ float g_w[2][NT];            // gate weight per slot per token
__device__ __align__(16) __half g_scr[2][NT][FF];   // per-slot expert outputs (fp16, 64 MiB)
__device__ __align__(16) __half g_xh[(size_t)NT * DM];          // fp16 x
__device__ __align__(16) __half g_wt[(size_t)NE * FF * DM];     // [e][n][k], fp16

// ======================= fused gate + We-transpose =======================
// blocks [0, 2048): gate, 8 tokens per block (one warp per token)
// blocks [2048, 4096): We transpose, 64x64 tile per block
__global__ void __launch_bounds__(256) gate_transpose_kernel(
        const float* __restrict__ x,
        const float* __restrict__ Wg,
        const float* __restrict__ bg,
        const float* __restrict__ We) {
    __shared__ float tile[64][65];

    if (blockIdx.x < 2048) {
        // ---------------- gate path ----------------
        int gwarp = (blockIdx.x * blockDim.x + threadIdx.x) >> 5;   // token id
        int lane  = threadIdx.x & 31;

        const float* xr = x + (size_t)gwarp * DM;
        // lane covers columns 2*lane + 64*i, i = 0..15 (float2 each)
        float2 xv[16];
#pragma unroll
        for (int i = 0; i < 16; i++)
            xv[i] = *(const float2*)&xr[2 * lane + 64 * i];

        // fp16 store: __half2 per (lane, i) — 4B/lane, coalesced
        __half* xh = g_xh + (size_t)gwarp * DM;
#pragma unroll
        for (int i = 0; i < 16; i++)
            *(__half2*)&xh[2 * lane + 64 * i] = __floats2half2_rn(xv[i].x, xv[i].y);

        float logits[NE];
#pragma unroll
        for (int e = 0; e < NE; e++) {
            const float* wg = Wg + e * DM;
            float acc = 0.f;
#pragma unroll
            for (int i = 0; i < 16; i++) {
                float2 w2 = *(const float2*)&wg[2 * lane + 64 * i];
                acc += xv[i].x * w2.x + xv[i].y * w2.y;
            }
#pragma unroll
            for (int o = 16; o > 0; o >>= 1) acc += __shfl_xor_sync(0xffffffffu, acc, o);
            logits[e] = acc + bg[e];
        }

        if (lane == 0) {
            int b0 = 0; float v0 = logits[0];
#pragma unroll
            for (int e = 1; e < NE; e++) if (logits[e] > v0) { v0 = logits[e]; b0 = e; }
            int b1 = -1; float v1 = -INFINITY;
#pragma unroll
            for (int e = 0; e < NE; e++) if (e != b0 && logits[e] > v1) { v1 = logits[e]; b1 = e; }

            g_w[0][gwarp] = 1.f / (1.f + expf(-v0));
            g_w[1][gwarp] = 1.f / (1.f + expf(-v1));

            int p0 = atomicAdd(&g_cnt[b0], 1);
            g_list[b0][p0] = gwarp;
            int p1 = atomicAdd(&g_cnt[b1], 1);
            g_list[b1][p1] = gwarp | (1 << 16);
        }
    } else {
        // ---------------- transpose path ----------------
        int id = blockIdx.x - 2048;        // 0..2047 = e(8) x kt(16) x nt(16)
        int e  = id >> 8;
        int kt = (id >> 4) & 15;
        int nt = id & 15;
        int k0 = kt * 64;
        int n0 = nt * 64;
        int tid = threadIdx.x;

        const float* src = We + (size_t)e * DM * FF;
        int r  = tid >> 4;        // 0..15
        int c4 = tid & 15;        // float4 column group
#pragma unroll
        for (int rr = 0; rr < 64; rr += 16) {
            float4 v = *(const float4*)&src[(size_t)(k0 + rr + r) * FF + n0 + c4 * 4];
            tile[rr + r][c4 * 4 + 0] = v.x;
            tile[rr + r][c4 * 4 + 1] = v.y;
            tile[rr + r][c4 * 4 + 2] = v.z;
            tile[rr + r][c4 * 4 + 3] = v.w;
        }
        __syncthreads();

        int nl = tid & 63;
        int ks = (tid >> 6) * 16;
        __half hbuf[16];
#pragma unroll
        for (int i = 0; i < 16; i++) hbuf[i] = __float2half_rn(tile[ks + i][nl]);
        __half* dst = g_wt + ((size_t)e * FF + n0 + nl) * DM + k0 + ks;
        *(uint4*)(dst + 0) = *(uint4*)(hbuf + 0);
        *(uint4*)(dst + 8) = *(uint4*)(hbuf + 8);
    }
}

// ======================= HMMA expert GEMM =======================
// smem layout (bytes):
//   [0,512)    s_entry (128 int)
//   [512,1024) s_w     (128 float)
//   [1024, +6*30720) 6 chunk-stages; per stage: A rows 0..127 then B rows 0..255,
//   each row 80B (64B data + 16B pad)
#define ROWB 80
#define ATILEB (128 * ROWB)      // 10240
#define STAGEB (384 * ROWB)      // 30720 (A 128 rows + B 256 rows)
#define NSTG 6
#define SM_TILES 1024
#define SM_TOTAL (SM_TILES + NSTG * STAGEB)   // 185344

__device__ __forceinline__ uint32_t smem_u32(const void* p) {
    uint32_t a;
    asm("{ .reg .u64 t; cvta.to.shared.u64 t, %1; cvt.u32.u64 %0, t; }" : "=r"(a) : "l"(p));
    return a;
}
#define CP_ASYNC16(dst, src) \
    asm volatile("cp.async.cg.shared.global [%0], [%1], 16;" :: "r"(dst), "l"(src))
#define CP_COMMIT() asm volatile("cp.async.commit_group;")
#define CP_WAIT1()  asm volatile("cp.async.wait_group 1;")
#define CP_WAIT0()  asm volatile("cp.async.wait_group 0;")

__device__ __forceinline__ void ldsm_x4(uint32_t a, uint32_t& r0, uint32_t& r1,
                                        uint32_t& r2, uint32_t& r3) {
    asm volatile("ldmatrix.sync.aligned.m8n8.x4.shared.b16 {%0,%1,%2,%3}, [%4];"
                 : "=r"(r0), "=r"(r1), "=r"(r2), "=r"(r3) : "r"(a));
}
__device__ __forceinline__ void mma16816(float* c, uint32_t a0, uint32_t a1,
                                         uint32_t a2, uint32_t a3,
                                         uint32_t b0, uint32_t b1) {
    asm volatile(
        "mma.sync.aligned.m16n8k16.row.col.f32.f16.f16.f32 "
        "{%0,%1,%2,%3}, {%4,%5,%6,%7}, {%8,%9}, {%0,%1,%2,%3};"
        : "+f"(c[0]), "+f"(c[1]), "+f"(c[2]), "+f"(c[3])
        : "r"(a0), "r"(a1), "r"(a2), "r"(a3), "r"(b0), "r"(b1));
}

__global__ void __launch_bounds__(256) expert_gemm_tc(const float* __restrict__ be) {
    extern __shared__ char smem[];
    int e   = blockIdx.z;
    int cnt = g_cnt[e];
    int m0  = blockIdx.x * BM;
    if (m0 >= cnt) return;
    int n0  = blockIdx.y * BN;

    int tid  = threadIdx.x;
    int wid  = tid >> 5;
    int lane = tid & 31;

    int*   s_entry = (int*)smem;
    float* s_w     = (float*)(smem + 512);

    // routing metadata for this row-block
    if (tid < BM) {
        int mi = m0 + tid;
        int entry = (mi < cnt) ? g_list[e][mi] : 0;
        s_entry[tid] = entry;
        s_w[tid]     = g_w[entry >> 16][entry & 0xFFFF];
    }
    __syncthreads();

    // ---- cp.async mapping: 1536 granules of 16B per stage (384 rows x 4) ----
    const char* src6[6];
    uint32_t    dst6[6];
    uint32_t sb = smem_u32(smem);
#pragma unroll
    for (int i = 0; i < 6; i++) {
        int g   = i * 256 + tid;
        int row = g >> 2;
        int q   = g & 3;
        const __half* base;
        if (row < 128) {
            base = g_xh + (size_t)(s_entry[row] & 0xFFFF) * DM;
        } else {
            base = g_wt + ((size_t)e * FF + n0 + (row - 128)) * DM;
        }
        src6[i] = (const char*)(base + q * 8);
        dst6[i] = sb + SM_TILES + (uint32_t)(row * ROWB + q * 16);
    }

#define FILL_STAGE(stoff, kbytes) do {                                             \
        uint32_t d = (stoff);                                                      \
        CP_ASYNC16(dst6[0] + d, src6[0] + (kbytes));                               \
        CP_ASYNC16(dst6[1] + d, src6[1] + (kbytes));                               \
        CP_ASYNC16(dst6[2] + d, src6[2] + (kbytes));                               \
        CP_ASYNC16(dst6[3] + d, src6[3] + (kbytes));                               \
        CP_ASYNC16(dst6[4] + d, src6[4] + (kbytes));                               \
        CP_ASYNC16(dst6[5] + d, src6[5] + (kbytes));                               \
    } while (0)

    // ---- ldmatrix per-lane offsets ----
    uint32_t a_lane = (uint32_t)((lane & 15) * ROWB + (lane >> 4) * 16);
    uint32_t b_lane = (uint32_t)(((lane >> 4) * 8 + (lane & 7)) * ROWB + ((lane >> 3) & 1) * 16);

    int wm = wid & 1;         // 2 warps in M (64 rows each)
    int wn = wid >> 1;        // 4 warps in N (64 cols each)
    uint32_t a_warp = a_lane + (uint32_t)(wm * 64) * ROWB;
    uint32_t b_warp = b_lane + (uint32_t)(wn * 64) * ROWB + ATILEB;

    float acc[4][8][4];
#pragma unroll
    for (int i = 0; i < 4; i++)
#pragma unroll
        for (int j = 0; j < 8; j++)
#pragma unroll
            for (int k = 0; k < 4; k++) acc[i][j][k] = 0.f;

    // fragments: single A buffer, double B buffer
    uint32_t a[4][4], b[2][4][4];

#define LOAD_A(Aw, kb) do {                                                        \
        _Pragma("unroll")                                                          \
        for (int mt = 0; mt < 4; mt++)                                             \
            ldsm_x4((Aw) + (uint32_t)(mt * 16) * ROWB + (kb),                      \
                    a[mt][0], a[mt][1], a[mt][2], a[mt][3]);                       \
    } while (0)
#define LOAD_B(buf, Bw, kb) do {                                                   \
        _Pragma("unroll")                                                          \
        for (int n2 = 0; n2 < 4; n2++)                                             \
            ldsm_x4((Bw) + (uint32_t)(n2 * 16) * ROWB + (kb),                      \
                    b[buf][n2][0], b[buf][n2][1], b[buf][n2][2], b[buf][n2][3]);   \
    } while (0)
#define DO_MMAS(buf) do {                                                          \
        _Pragma("unroll")                                                          \
        for (int mt = 0; mt < 4; mt++)                                             \
            _Pragma("unroll")                                                      \
            for (int n2 = 0; n2 < 4; n2++) {                                       \
                mma16816(acc[mt][n2 * 2 + 0],                                      \
                         a[mt][0], a[mt][1], a[mt][2], a[mt][3],                   \
                         b[buf][n2][0], b[buf][n2][1]);                            \
                mma16816(acc[mt][n2 * 2 + 1],                                      \
                         a[mt][0], a[mt][1], a[mt][2], a[mt][3],                   \
                         b[buf][n2][2], b[buf][n2][3]);                            \
            }                                                                      \
    } while (0)

    // prologue: pairs 0 and 1 in flight (2 groups)
    FILL_STAGE(0, 0);
    FILL_STAGE(STAGEB, BK * 2);
    CP_COMMIT();
    FILL_STAGE(2 * STAGEB, 2 * BK * 2);
    FILL_STAGE(3 * STAGEB, 3 * BK * 2);
    CP_COMMIT();

    for (int p = 0; p < PAIRS; ++p) {
        if (p + 1 < PAIRS) { CP_WAIT1(); } else { CP_WAIT0(); }
        __syncthreads();
        if (p + 2 < PAIRS) {
            int c2 = 2 * (p + 2);
            FILL_STAGE((uint32_t)(c2 % NSTG) * STAGEB, c2 * BK * 2);
            FILL_STAGE((uint32_t)((c2 + 1) % NSTG) * STAGEB, (c2 + 1) * BK * 2);
            CP_COMMIT();
        }

        int c0 = 2 * p;
        uint32_t st0 = sb + SM_TILES + (uint32_t)(c0 % NSTG) * STAGEB;
        uint32_t st1 = sb + SM_TILES + (uint32_t)((c0 + 1) % NSTG) * STAGEB;
        uint32_t Aw0 = st0 + a_warp, Bw0 = st0 + b_warp;
        uint32_t Aw1 = st1 + a_warp, Bw1 = st1 + b_warp;

        // software-pipelined pair: only the first load group is latency-exposed
        LOAD_A(Aw0, 0u);
        LOAD_B(0, Bw0, 0u);
        LOAD_B(1, Bw0, 32u);
        DO_MMAS(0);                 // (A c0k0, B c0k0)
        LOAD_A(Aw0, 32u);           // A c0k1
        LOAD_B(0, Bw1, 0u);         // B c1k0 into freed buf0
        DO_MMAS(1);                 // (A c0k1, B c0k1)
        LOAD_A(Aw1, 0u);            // A c1k0
        LOAD_B(1, Bw1, 32u);        // B c1k1
        DO_MMAS(0);                 // (A c1k0, B c1k0)
        LOAD_A(Aw1, 32u);           // A c1k1
        DO_MMAS(1);                 // (A c1k1, B c1k1)
    }

    // ---- epilogue (fp16 scratch) ----
    int qrow = lane >> 2;          // 0..7
    int qcol = (lane & 3) * 2;     // 0,2,4,6
    float2 bias2[8];
#pragma unroll
    for (int nt = 0; nt < 8; nt++) {
        int nc = n0 + wn * 64 + nt * 8 + qcol;
        bias2[nt] = make_float2(be[e * FF + nc], be[e * FF + nc + 1]);
    }
#pragma unroll
    for (int mt = 0; mt < 4; mt++) {
#pragma unroll
        for (int half = 0; half < 2; half++) {
            int mrow = wm * 64 + mt * 16 + half * 8 + qrow;
            if (m0 + mrow < cnt) {
                int entry = s_entry[mrow];
                int tok   = entry & 0xFFFF;
                int slot  = entry >> 16;
                float w   = s_w[mrow];
#pragma unroll
                for (int nt = 0; nt < 8; nt++) {
                    int nc = n0 + wn * 64 + nt * 8 + qcol;
                    float ox = (acc[mt][nt][half * 2 + 0] + bias2[nt].x) * w;
                    float oy = (acc[mt][nt][half * 2 + 1] + bias2[nt].y) * w;
                    *(__half2*)&g_scr[slot][tok][nc] = __floats2half2_rn(ox, oy);
                }
            }
        }
    }
}

// out = scr[0] + scr[1]  (fp16 -> fp32), 8 elements per thread
__global__ void combine_kernel(float* __restrict__ out) {
    size_t j = (size_t)blockIdx.x * blockDim.x + threadIdx.x;  // one uint4 = 8 halves
    uint4 ua = ((const uint4*)g_scr[0])[j];
    uint4 ub = ((const uint4*)g_scr[1])[j];
    float2 a0 = __half22float2(*(__half2*)&ua.x);
    float2 a1 = __half22float2(*(__half2*)&ua.y);
    float2 a2 = __half22float2(*(__half2*)&ua.z);
    float2 a3 = __half22float2(*(__half2*)&ua.w);
    float2 b0 = __half22float2(*(__half2*)&ub.x);
    float2 b1 = __half22float2(*(__half2*)&ub.y);
    float2 b2 = __half22float2(*(__half2*)&ub.z);
    float2 b3 = __half22float2(*(__half2*)&ub.w);
    float4* o = (float4*)out + 2 * j;
    o[0] = make_float4(a0.x + b0.x, a0.y + b0.y, a1.x + b1.x, a1.y + b1.y);
    o[1] = make_float4(a2.x + b2.x, a2.y + b2.y, a3.x + b3.x, a3.y + b3.y);
}

extern "C" void kernel_launch(void* const* d_in, const int* in_sizes, int n_in,
                              void* d_out, int out_size) {
    const float* x  = (const float*)d_in[0];   // (4,4096,1024)
    const float* Wg = (const float*)d_in[1];   // (8,1024)
    const float* bg = (const float*)d_in[2];   // (8,)
    const float* We = (const float*)d_in[3];   // (8,1024,1024)
    const float* be = (const float*)d_in[4];   // (8,1024)
    float* out = (float*)d_out;                // (4,4096,1024) f32

    // zero expert counters via memset node (graph-capturable, no launch)
    void* cnt_addr = nullptr;
    cudaGetSymbolAddress(&cnt_addr, g_cnt);
    cudaMemsetAsync(cnt_addr, 0, NE * sizeof(int));

    gate_transpose_kernel<<<4096, 256>>>(x, Wg, bg, We);

    cudaFuncSetAttribute(expert_gemm_tc, cudaFuncAttributeMaxDynamicSharedMemorySize, SM_TOTAL);
    expert_gemm_tc<<<dim3(NT / BM, FF / BN, NE), 256, SM_TOTAL>>>(be);

    combine_kernel<<<(NT * FF / 8) / 256, 256>>>(out);
}

// round 16
// speedup vs baseline: 1.2540x; 1.0180x over previous
#include <cuda_runtime.h>
#include <cuda_fp16.h>
#include <math.h>
#include <stdint.h>

#define NT 16384      // tokens = 4 * 4096
#define DM 1024       // d_model
#define FF 1024       // d_out
#define NE 8          // experts

// GEMM tiling
#define BM 128
#define BN 256
#define BK 32
#define CHUNKS (DM / BK)      // 32
#define PAIRS (CHUNKS / 2)    // 16

// ---- device scratch (static, allocation-free) ----
__device__ int   g_cnt[NE];
__device__ int   g_list[NE][NT];        // packed: token | (slot<<16)
__device__ float g_w[2][NT];            // gate weight per slot per token
__device__ __align__(16) __half g_scr[2][NT][FF];   // per-slot expert outputs (fp16, 64 MiB)
__device__ __align__(16) __half g_xh[(size_t)NT * DM];          // fp16 x
__device__ __align__(16) __half g_wt[(size_t)NE * FF * DM];     // [e][n][k], fp16

// ======================= fused gate + We-transpose =======================
// blocks [0, 2048): gate, 8 tokens per block (one warp per token)
// blocks [2048, 4096): We transpose, 64x64 tile per block
__global__ void __launch_bounds__(256) gate_transpose_kernel(
        const float* __restrict__ x,
        const float* __restrict__ Wg,
        const float* __restrict__ bg,
        const float* __restrict__ We) {
    __shared__ float tile[64][65];

    if (blockIdx.x < 2048) {
        // ---------------- gate path ----------------
        int gwarp = (blockIdx.x * blockDim.x + threadIdx.x) >> 5;   // token id
        int lane  = threadIdx.x & 31;

        const float* xr = x + (size_t)gwarp * DM + 4 * lane;
        // lane covers columns 4*lane + 128*i, i = 0..7 (float4 each)
        float4 xv[8];
#pragma unroll
        for (int i = 0; i < 8; i++)
            xv[i] = *(const float4*)&xr[128 * i];

        // fp16 store: 4 halves (uint2) per (lane, i)
        __half* xh = g_xh + (size_t)gwarp * DM + 4 * lane;
#pragma unroll
        for (int i = 0; i < 8; i++) {
            __half2 h01 = __floats2half2_rn(xv[i].x, xv[i].y);
            __half2 h23 = __floats2half2_rn(xv[i].z, xv[i].w);
            uint2 pk;
            pk.x = *(uint32_t*)&h01;
            pk.y = *(uint32_t*)&h23;
            *(uint2*)&xh[128 * i] = pk;
        }

        float logits[NE];
#pragma unroll
        for (int e = 0; e < NE; e++) {
            const float* wg = Wg + e * DM + 4 * lane;
            float a0 = 0.f, a1 = 0.f;   // two partials: halves the FFMA chain depth
#pragma unroll
            for (int i = 0; i < 4; i++) {
                float4 w0 = *(const float4*)&wg[256 * i];
                float4 w1 = *(const float4*)&wg[256 * i + 128];
                a0 += xv[2 * i].x * w0.x + xv[2 * i].y * w0.y
                    + xv[2 * i].z * w0.z + xv[2 * i].w * w0.w;
                a1 += xv[2 * i + 1].x * w1.x + xv[2 * i + 1].y * w1.y
                    + xv[2 * i + 1].z * w1.z + xv[2 * i + 1].w * w1.w;
            }
            float acc = a0 + a1;
#pragma unroll
            for (int o = 16; o > 0; o >>= 1) acc += __shfl_xor_sync(0xffffffffu, acc, o);
            logits[e] = acc + bg[e];
        }

        if (lane == 0) {
            int b0 = 0; float v0 = logits[0];
#pragma unroll
            for (int e = 1; e < NE; e++) if (logits[e] > v0) { v0 = logits[e]; b0 = e; }
            int b1 = -1; float v1 = -INFINITY;
#pragma unroll
            for (int e = 0; e < NE; e++) if (e != b0 && logits[e] > v1) { v1 = logits[e]; b1 = e; }

            g_w[0][gwarp] = 1.f / (1.f + expf(-v0));
            g_w[1][gwarp] = 1.f / (1.f + expf(-v1));

            int p0 = atomicAdd(&g_cnt[b0], 1);
            g_list[b0][p0] = gwarp;
            int p1 = atomicAdd(&g_cnt[b1], 1);
            g_list[b1][p1] = gwarp | (1 << 16);
        }
    } else {
        // ---------------- transpose path ----------------
        int id = blockIdx.x - 2048;        // 0..2047 = e(8) x kt(16) x nt(16)
        int e  = id >> 8;
        int kt = (id >> 4) & 15;
        int nt = id & 15;
        int k0 = kt * 64;
        int n0 = nt * 64;
        int tid = threadIdx.x;

        const float* src = We + (size_t)e * DM * FF;
        int r  = tid >> 4;        // 0..15
        int c4 = tid & 15;        // float4 column group
#pragma unroll
        for (int rr = 0; rr < 64; rr += 16) {
            float4 v = *(const float4*)&src[(size_t)(k0 + rr + r) * FF + n0 + c4 * 4];
            tile[rr + r][c4 * 4 + 0] = v.x;
            tile[rr + r][c4 * 4 + 1] = v.y;
            tile[rr + r][c4 * 4 + 2] = v.z;
            tile[rr + r][c4 * 4 + 3] = v.w;
        }
        __syncthreads();

        int nl = tid & 63;
        int ks = (tid >> 6) * 16;
        __half hbuf[16];
#pragma unroll
        for (int i = 0; i < 16; i++) hbuf[i] = __float2half_rn(tile[ks + i][nl]);
        __half* dst = g_wt + ((size_t)e * FF + n0 + nl) * DM + k0 + ks;
        *(uint4*)(dst + 0) = *(uint4*)(hbuf + 0);
        *(uint4*)(dst + 8) = *(uint4*)(hbuf + 8);
    }
}

// ======================= HMMA expert GEMM =======================
// smem layout (bytes):
//   [0,512)    s_entry (128 int)
//   [512,1024) s_w     (128 float)
//   [1024, +6*30720) 6 chunk-stages; per stage: A rows 0..127 then B rows 0..255,
//   each row 80B (64B data + 16B pad)
#define ROWB 80
#define ATILEB (128 * ROWB)      // 10240
#define STAGEB (384 * ROWB)      // 30720 (A 128 rows + B 256 rows)
#define NSTG 6
#define SM_TILES 1024
#define SM_TOTAL (SM_TILES + NSTG * STAGEB)   // 185344

__device__ __forceinline__ uint32_t smem_u32(const void* p) {
    uint32_t a;
    asm("{ .reg .u64 t; cvta.to.shared.u64 t, %1; cvt.u32.u64 %0, t; }" : "=r"(a) : "l"(p));
    return a;
}
#define CP_ASYNC16(dst, src) \
    asm volatile("cp.async.cg.shared.global [%0], [%1], 16;" :: "r"(dst), "l"(src))
#define CP_COMMIT() asm volatile("cp.async.commit_group;")
#define CP_WAIT1()  asm volatile("cp.async.wait_group 1;")
#define CP_WAIT0()  asm volatile("cp.async.wait_group 0;")

__device__ __forceinline__ void ldsm_x4(uint32_t a, uint32_t& r0, uint32_t& r1,
                                        uint32_t& r2, uint32_t& r3) {
    asm volatile("ldmatrix.sync.aligned.m8n8.x4.shared.b16 {%0,%1,%2,%3}, [%4];"
                 : "=r"(r0), "=r"(r1), "=r"(r2), "=r"(r3) : "r"(a));
}
__device__ __forceinline__ void mma16816(float* c, uint32_t a0, uint32_t a1,
                                         uint32_t a2, uint32_t a3,
                                         uint32_t b0, uint32_t b1) {
    asm volatile(
        "mma.sync.aligned.m16n8k16.row.col.f32.f16.f16.f32 "
        "{%0,%1,%2,%3}, {%4,%5,%6,%7}, {%8,%9}, {%0,%1,%2,%3};"
        : "+f"(c[0]), "+f"(c[1]), "+f"(c[2]), "+f"(c[3])
        : "r"(a0), "r"(a1), "r"(a2), "r"(a3), "r"(b0), "r"(b1));
}

__global__ void __launch_bounds__(256) expert_gemm_tc(const float* __restrict__ be) {
    extern __shared__ char smem[];
    int e   = blockIdx.z;
    int cnt = g_cnt[e];
    int m0  = blockIdx.x * BM;
    if (m0 >= cnt) return;
    int n0  = blockIdx.y * BN;

    int tid  = threadIdx.x;
    int wid  = tid >> 5;
    int lane = tid & 31;

    int*   s_entry = (int*)smem;
    float* s_w     = (float*)(smem + 512);

    // routing metadata for this row-block
    if (tid < BM) {
        int mi = m0 + tid;
        int entry = (mi < cnt) ? g_list[e][mi] : 0;
        s_entry[tid] = entry;
        s_w[tid]     = g_w[entry >> 16][entry & 0xFFFF];
    }
    __syncthreads();

    // ---- cp.async mapping: 1536 granules of 16B per stage (384 rows x 4) ----
    const char* src6[6];
    uint32_t    dst6[6];
    uint32_t sb = smem_u32(smem);
#pragma unroll
    for (int i = 0; i < 6; i++) {
        int g   = i * 256 + tid;
        int row = g >> 2;
        int q   = g & 3;
        const __half* base;
        if (row < 128) {
            base = g_xh + (size_t)(s_entry[row] & 0xFFFF) * DM;
        } else {
            base = g_wt + ((size_t)e * FF + n0 + (row - 128)) * DM;
        }
        src6[i] = (const char*)(base + q * 8);
        dst6[i] = sb + SM_TILES + (uint32_t)(row * ROWB + q * 16);
    }

#define FILL_STAGE(stoff, kbytes) do {                                             \
        uint32_t d = (stoff);                                                      \
        CP_ASYNC16(dst6[0] + d, src6[0] + (kbytes));                               \
        CP_ASYNC16(dst6[1] + d, src6[1] + (kbytes));                               \
        CP_ASYNC16(dst6[2] + d, src6[2] + (kbytes));                               \
        CP_ASYNC16(dst6[3] + d, src6[3] + (kbytes));                               \
        CP_ASYNC16(dst6[4] + d, src6[4] + (kbytes));                               \
        CP_ASYNC16(dst6[5] + d, src6[5] + (kbytes));                               \
    } while (0)

    // ---- ldmatrix per-lane offsets ----
    uint32_t a_lane = (uint32_t)((lane & 15) * ROWB + (lane >> 4) * 16);
    uint32_t b_lane = (uint32_t)(((lane >> 4) * 8 + (lane & 7)) * ROWB + ((lane >> 3) & 1) * 16);

    int wm = wid & 1;         // 2 warps in M (64 rows each)
    int wn = wid >> 1;        // 4 warps in N (64 cols each)
    uint32_t a_warp = a_lane + (uint32_t)(wm * 64) * ROWB;
    uint32_t b_warp = b_lane + (uint32_t)(wn * 64) * ROWB + ATILEB;

    float acc[4][8][4];
#pragma unroll
    for (int i = 0; i < 4; i++)
#pragma unroll
        for (int j = 0; j < 8; j++)
#pragma unroll
            for (int k = 0; k < 4; k++) acc[i][j][k] = 0.f;

    // fragments: single A buffer, double B buffer
    uint32_t a[4][4], b[2][4][4];

#define LOAD_A(Aw, kb) do {                                                        \
        _Pragma("unroll")                                                          \
        for (int mt = 0; mt < 4; mt++)                                             \
            ldsm_x4((Aw) + (uint32_t)(mt * 16) * ROWB + (kb),                      \
                    a[mt][0], a[mt][1], a[mt][2], a[mt][3]);                       \
    } while (0)
#define LOAD_B(buf, Bw, kb) do {                                                   \
        _Pragma("unroll")                                                          \
        for (int n2 = 0; n2 < 4; n2++)                                             \
            ldsm_x4((Bw) + (uint32_t)(n2 * 16) * ROWB + (kb),                      \
                    b[buf][n2][0], b[buf][n2][1], b[buf][n2][2], b[buf][n2][3]);   \
    } while (0)
#define DO_MMAS(buf) do {                                                          \
        _Pragma("unroll")                                                          \
        for (int mt = 0; mt < 4; mt++)                                             \
            _Pragma("unroll")                                                      \
            for (int n2 = 0; n2 < 4; n2++) {                                       \
                mma16816(acc[mt][n2 * 2 + 0],                                      \
                         a[mt][0], a[mt][1], a[mt][2], a[mt][3],                   \
                         b[buf][n2][0], b[buf][n2][1]);                            \
                mma16816(acc[mt][n2 * 2 + 1],                                      \
                         a[mt][0], a[mt][1], a[mt][2], a[mt][3],                   \
                         b[buf][n2][2], b[buf][n2][3]);                            \
            }                                                                      \
    } while (0)

    // prologue: pairs 0 and 1 in flight (2 groups)
    FILL_STAGE(0, 0);
    FILL_STAGE(STAGEB, BK * 2);
    CP_COMMIT();
    FILL_STAGE(2 * STAGEB, 2 * BK * 2);
    FILL_STAGE(3 * STAGEB, 3 * BK * 2);
    CP_COMMIT();

    for (int p = 0; p < PAIRS; ++p) {
        if (p + 1 < PAIRS) { CP_WAIT1(); } else { CP_WAIT0(); }
        __syncthreads();
        if (p + 2 < PAIRS) {
            int c2 = 2 * (p + 2);
            FILL_STAGE((uint32_t)(c2 % NSTG) * STAGEB, c2 * BK * 2);
            FILL_STAGE((uint32_t)((c2 + 1) % NSTG) * STAGEB, (c2 + 1) * BK * 2);
            CP_COMMIT();
        }

        int c0 = 2 * p;
        uint32_t st0 = sb + SM_TILES + (uint32_t)(c0 % NSTG) * STAGEB;
        uint32_t st1 = sb + SM_TILES + (uint32_t)((c0 + 1) % NSTG) * STAGEB;
        uint32_t Aw0 = st0 + a_warp, Bw0 = st0 + b_warp;
        uint32_t Aw1 = st1 + a_warp, Bw1 = st1 + b_warp;

        // software-pipelined pair: only the first load group is latency-exposed
        LOAD_A(Aw0, 0u);
        LOAD_B(0, Bw0, 0u);
        LOAD_B(1, Bw0, 32u);
        DO_MMAS(0);                 // (A c0k0, B c0k0)
        LOAD_A(Aw0, 32u);           // A c0k1
        LOAD_B(0, Bw1, 0u);         // B c1k0 into freed buf0
        DO_MMAS(1);                 // (A c0k1, B c0k1)
        LOAD_A(Aw1, 0u);            // A c1k0
        LOAD_B(1, Bw1, 32u);        // B c1k1
        DO_MMAS(0);                 // (A c1k0, B c1k0)
        LOAD_A(Aw1, 32u);           // A c1k1
        DO_MMAS(1);                 // (A c1k1, B c1k1)
    }

    // ---- epilogue (fp16 scratch) ----
    int qrow = lane >> 2;          // 0..7
    int qcol = (lane & 3) * 2;     // 0,2,4,6
    float2 bias2[8];
#pragma unroll
    for (int nt = 0; nt < 8; nt++) {
        int nc = n0 + wn * 64 + nt * 8 + qcol;
        bias2[nt] = make_float2(be[e * FF + nc], be[e * FF + nc + 1]);
    }
#pragma unroll
    for (int mt = 0; mt < 4; mt++) {
#pragma unroll
        for (int half = 0; half < 2; half++) {
            int mrow = wm * 64 + mt * 16 + half * 8 + qrow;
            if (m0 + mrow < cnt) {
                int entry = s_entry[mrow];
                int tok   = entry & 0xFFFF;
                int slot  = entry >> 16;
                float w   = s_w[mrow];
#pragma unroll
                for (int nt = 0; nt < 8; nt++) {
                    int nc = n0 + wn * 64 + nt * 8 + qcol;
                    float ox = (acc[mt][nt][half * 2 + 0] + bias2[nt].x) * w;
                    float oy = (acc[mt][nt][half * 2 + 1] + bias2[nt].y) * w;
                    *(__half2*)&g_scr[slot][tok][nc] = __floats2half2_rn(ox, oy);
                }
            }
        }
    }
}

// out = scr[0] + scr[1]  (fp16 -> fp32), 8 elements per thread
__global__ void combine_kernel(float* __restrict__ out) {
    size_t j = (size_t)blockIdx.x * blockDim.x + threadIdx.x;  // one uint4 = 8 halves
    uint4 ua = ((const uint4*)g_scr[0])[j];
    uint4 ub = ((const uint4*)g_scr[1])[j];
    float2 a0 = __half22float2(*(__half2*)&ua.x);
    float2 a1 = __half22float2(*(__half2*)&ua.y);
    float2 a2 = __half22float2(*(__half2*)&ua.z);
    float2 a3 = __half22float2(*(__half2*)&ua.w);
    float2 b0 = __half22float2(*(__half2*)&ub.x);
    float2 b1 = __half22float2(*(__half2*)&ub.y);
    float2 b2 = __half22float2(*(__half2*)&ub.z);
    float2 b3 = __half22float2(*(__half2*)&ub.w);
    float4* o = (float4*)out + 2 * j;
    o[0] = make_float4(a0.x + b0.x, a0.y + b0.y, a1.x + b1.x, a1.y + b1.y);
    o[1] = make_float4(a2.x + b2.x, a2.y + b2.y, a3.x + b3.x, a3.y + b3.y);
}

extern "C" void kernel_launch(void* const* d_in, const int* in_sizes, int n_in,
                              void* d_out, int out_size) {
    const float* x  = (const float*)d_in[0];   // (4,4096,1024)
    const float* Wg = (const float*)d_in[1];   // (8,1024)
    const float* bg = (const float*)d_in[2];   // (8,)
    const float* We = (const float*)d_in[3];   // (8,1024,1024)
    const float* be = (const float*)d_in[4];   // (8,1024)
    float* out = (float*)d_out;                // (4,4096,1024) f32

    // zero expert counters via memset node (graph-capturable, no launch)
    void* cnt_addr = nullptr;
    cudaGetSymbolAddress(&cnt_addr, g_cnt);
    cudaMemsetAsync(cnt_addr, 0, NE * sizeof(int));

    gate_transpose_kernel<<<4096, 256>>>(x, Wg, bg, We);

    cudaFuncSetAttribute(expert_gemm_tc, cudaFuncAttributeMaxDynamicSharedMemorySize, SM_TOTAL);
    expert_gemm_tc<<<dim3(NT / BM, FF / BN, NE), 256, SM_TOTAL>>>(be);

    combine_kernel<<<(NT * FF / 8) / 256, 256>>>(out);
}

// round 17
// speedup vs baseline: 1.2639x; 1.0079x over previous
#include <cuda_runtime.h>
#include <cuda_fp16.h>
#include <math.h>
#include <stdint.h>

#define NT 16384      // tokens = 4 * 4096
#define DM 1024       // d_model
#define FF 1024       // d_out
#define NE 8          // experts

// GEMM tiling
#define BM 128
#define BN 256
#define BK 32
#define CHUNKS (DM / BK)      // 32
#define PAIRS (CHUNKS / 2)    // 16

// ---- device scratch (static, allocation-free) ----
__device__ int   g_cnt[NE];
__device__ int   g_list[NE][NT];        // packed: token | (slot<<16)
__device__ float g_w[2][NT];            // gate weight per slot per token
__device__ __align__(16) __half g_scr[2][NT][FF];   // per-slot expert outputs (fp16, 64 MiB)
__device__ __align__(16) __half g_xh[(size_t)NT * DM];          // fp16 x
__device__ __align__(16) __half g_wt[(size_t)NE * FF * DM];     // [e][n][k], fp16

// ======================= fused gate + We-transpose =======================
// blocks [0, 2048): gate, 8 tokens per block (one warp per token)
// blocks [2048, 4096): We transpose, 64x64 tile per block
__global__ void __launch_bounds__(256) gate_transpose_kernel(
        const float* __restrict__ x,
        const float* __restrict__ Wg,
        const float* __restrict__ bg,
        const float* __restrict__ We) {
    __shared__ float tile[64][65];

    if (blockIdx.x < 2048) {
        // ---------------- gate path (streaming; low register pressure) ----------------
        int gwarp = (blockIdx.x * blockDim.x + threadIdx.x) >> 5;   // token id
        int lane  = threadIdx.x & 31;

        const float* xr = x + (size_t)gwarp * DM + 4 * lane;
        __half*      xh = g_xh + (size_t)gwarp * DM + 4 * lane;
        const float* wg = Wg + 4 * lane;

        float acc[NE];
#pragma unroll
        for (int e = 0; e < NE; e++) acc[e] = 0.f;

        // stream 8 groups of float4; xv is NOT kept live across groups
#pragma unroll
        for (int i = 0; i < 8; i++) {
            float4 xv = *(const float4*)&xr[128 * i];

            // fp16 store
            __half2 h01 = __floats2half2_rn(xv.x, xv.y);
            __half2 h23 = __floats2half2_rn(xv.z, xv.w);
            uint2 pk;
            pk.x = *(uint32_t*)&h01;
            pk.y = *(uint32_t*)&h23;
            *(uint2*)&xh[128 * i] = pk;

            // accumulate all 8 experts (independent chains -> ILP)
#pragma unroll
            for (int e = 0; e < NE; e++) {
                float4 w = *(const float4*)&wg[(size_t)e * DM + 128 * i];
                acc[e] += xv.x * w.x + xv.y * w.y + xv.z * w.z + xv.w * w.w;
            }
        }

        float logits[NE];
#pragma unroll
        for (int e = 0; e < NE; e++) {
            float a = acc[e];
#pragma unroll
            for (int o = 16; o > 0; o >>= 1) a += __shfl_xor_sync(0xffffffffu, a, o);
            logits[e] = a + bg[e];
        }

        if (lane == 0) {
            int b0 = 0; float v0 = logits[0];
#pragma unroll
            for (int e = 1; e < NE; e++) if (logits[e] > v0) { v0 = logits[e]; b0 = e; }
            int b1 = -1; float v1 = -INFINITY;
#pragma unroll
            for (int e = 0; e < NE; e++) if (e != b0 && logits[e] > v1) { v1 = logits[e]; b1 = e; }

            g_w[0][gwarp] = 1.f / (1.f + expf(-v0));
            g_w[1][gwarp] = 1.f / (1.f + expf(-v1));

            int p0 = atomicAdd(&g_cnt[b0], 1);
            g_list[b0][p0] = gwarp;
            int p1 = atomicAdd(&g_cnt[b1], 1);
            g_list[b1][p1] = gwarp | (1 << 16);
        }
    } else {
        // ---------------- transpose path ----------------
        int id = blockIdx.x - 2048;        // 0..2047 = e(8) x kt(16) x nt(16)
        int e  = id >> 8;
        int kt = (id >> 4) & 15;
        int nt = id & 15;
        int k0 = kt * 64;
        int n0 = nt * 64;
        int tid = threadIdx.x;

        const float* src = We + (size_t)e * DM * FF;
        int r  = tid >> 4;        // 0..15
        int c4 = tid & 15;        // float4 column group
#pragma unroll
        for (int rr = 0; rr < 64; rr += 16) {
            float4 v = *(const float4*)&src[(size_t)(k0 + rr + r) * FF + n0 + c4 * 4];
            tile[rr + r][c4 * 4 + 0] = v.x;
            tile[rr + r][c4 * 4 + 1] = v.y;
            tile[rr + r][c4 * 4 + 2] = v.z;
            tile[rr + r][c4 * 4 + 3] = v.w;
        }
        __syncthreads();

        int nl = tid & 63;
        int ks = (tid >> 6) * 16;
        __half hbuf[16];
#pragma unroll
        for (int i = 0; i < 16; i++) hbuf[i] = __float2half_rn(tile[ks + i][nl]);
        __half* dst = g_wt + ((size_t)e * FF + n0 + nl) * DM + k0 + ks;
        *(uint4*)(dst + 0) = *(uint4*)(hbuf + 0);
        *(uint4*)(dst + 8) = *(uint4*)(hbuf + 8);
    }
}

// ======================= HMMA expert GEMM =======================
// smem layout (bytes):
//   [0,512)    s_entry (128 int)
//   [512,1024) s_w     (128 float)
//   [1024, +6*30720) 6 chunk-stages; per stage: A rows 0..127 then B rows 0..255,
//   each row 80B (64B data + 16B pad)
#define ROWB 80
#define ATILEB (128 * ROWB)      // 10240
#define STAGEB (384 * ROWB)      // 30720 (A 128 rows + B 256 rows)
#define NSTG 6
#define SM_TILES 1024
#define SM_TOTAL (SM_TILES + NSTG * STAGEB)   // 185344

__device__ __forceinline__ uint32_t smem_u32(const void* p) {
    uint32_t a;
    asm("{ .reg .u64 t; cvta.to.shared.u64 t, %1; cvt.u32.u64 %0, t; }" : "=r"(a) : "l"(p));
    return a;
}
#define CP_ASYNC16(dst, src) \
    asm volatile("cp.async.cg.shared.global [%0], [%1], 16;" :: "r"(dst), "l"(src))
#define CP_COMMIT() asm volatile("cp.async.commit_group;")
#define CP_WAIT1()  asm volatile("cp.async.wait_group 1;")
#define CP_WAIT0()  asm volatile("cp.async.wait_group 0;")

__device__ __forceinline__ void ldsm_x4(uint32_t a, uint32_t& r0, uint32_t& r1,
                                        uint32_t& r2, uint32_t& r3) {
    asm volatile("ldmatrix.sync.aligned.m8n8.x4.shared.b16 {%0,%1,%2,%3}, [%4];"
                 : "=r"(r0), "=r"(r1), "=r"(r2), "=r"(r3) : "r"(a));
}
__device__ __forceinline__ void mma16816(float* c, uint32_t a0, uint32_t a1,
                                         uint32_t a2, uint32_t a3,
                                         uint32_t b0, uint32_t b1) {
    asm volatile(
        "mma.sync.aligned.m16n8k16.row.col.f32.f16.f16.f32 "
        "{%0,%1,%2,%3}, {%4,%5,%6,%7}, {%8,%9}, {%0,%1,%2,%3};"
        : "+f"(c[0]), "+f"(c[1]), "+f"(c[2]), "+f"(c[3])
        : "r"(a0), "r"(a1), "r"(a2), "r"(a3), "r"(b0), "r"(b1));
}

__global__ void __launch_bounds__(256) expert_gemm_tc(const float* __restrict__ be) {
    extern __shared__ char smem[];
    int e   = blockIdx.z;
    int cnt = g_cnt[e];
    int m0  = blockIdx.x * BM;
    if (m0 >= cnt) return;
    int n0  = blockIdx.y * BN;

    int tid  = threadIdx.x;
    int wid  = tid >> 5;
    int lane = tid & 31;

    int*   s_entry = (int*)smem;
    float* s_w     = (float*)(smem + 512);

    // routing metadata for this row-block
    if (tid < BM) {
        int mi = m0 + tid;
        int entry = (mi < cnt) ? g_list[e][mi] : 0;
        s_entry[tid] = entry;
        s_w[tid]     = g_w[entry >> 16][entry & 0xFFFF];
    }
    __syncthreads();

    // ---- cp.async mapping: 1536 granules of 16B per stage (384 rows x 4) ----
    const char* src6[6];
    uint32_t    dst6[6];
    uint32_t sb = smem_u32(smem);
#pragma unroll
    for (int i = 0; i < 6; i++) {
        int g   = i * 256 + tid;
        int row = g >> 2;
        int q   = g & 3;
        const __half* base;
        if (row < 128) {
            base = g_xh + (size_t)(s_entry[row] & 0xFFFF) * DM;
        } else {
            base = g_wt + ((size_t)e * FF + n0 + (row - 128)) * DM;
        }
        src6[i] = (const char*)(base + q * 8);
        dst6[i] = sb + SM_TILES + (uint32_t)(row * ROWB + q * 16);
    }

#define FILL_STAGE(stoff, kbytes) do {                                             \
        uint32_t d = (stoff);                                                      \
        CP_ASYNC16(dst6[0] + d, src6[0] + (kbytes));                               \
        CP_ASYNC16(dst6[1] + d, src6[1] + (kbytes));                               \
        CP_ASYNC16(dst6[2] + d, src6[2] + (kbytes));                               \
        CP_ASYNC16(dst6[3] + d, src6[3] + (kbytes));                               \
        CP_ASYNC16(dst6[4] + d, src6[4] + (kbytes));                               \
        CP_ASYNC16(dst6[5] + d, src6[5] + (kbytes));                               \
    } while (0)

    // ---- ldmatrix per-lane offsets ----
    uint32_t a_lane = (uint32_t)((lane & 15) * ROWB + (lane >> 4) * 16);
    uint32_t b_lane = (uint32_t)(((lane >> 4) * 8 + (lane & 7)) * ROWB + ((lane >> 3) & 1) * 16);

    int wm = wid & 1;         // 2 warps in M (64 rows each)
    int wn = wid >> 1;        // 4 warps in N (64 cols each)
    uint32_t a_warp = a_lane + (uint32_t)(wm * 64) * ROWB;
    uint32_t b_warp = b_lane + (uint32_t)(wn * 64) * ROWB + ATILEB;

    float acc[4][8][4];
#pragma unroll
    for (int i = 0; i < 4; i++)
#pragma unroll
        for (int j = 0; j < 8; j++)
#pragma unroll
            for (int k = 0; k < 4; k++) acc[i][j][k] = 0.f;

    // fragments: single A buffer, double B buffer
    uint32_t a[4][4], b[2][4][4];

#define LOAD_A(Aw, kb) do {                                                        \
        _Pragma("unroll")                                                          \
        for (int mt = 0; mt < 4; mt++)                                             \
            ldsm_x4((Aw) + (uint32_t)(mt * 16) * ROWB + (kb),                      \
                    a[mt][0], a[mt][1], a[mt][2], a[mt][3]);                       \
    } while (0)
#define LOAD_B(buf, Bw, kb) do {                                                   \
        _Pragma("unroll")                                                          \
        for (int n2 = 0; n2 < 4; n2++)                                             \
            ldsm_x4((Bw) + (uint32_t)(n2 * 16) * ROWB + (kb),                      \
                    b[buf][n2][0], b[buf][n2][1], b[buf][n2][2], b[buf][n2][3]);   \
    } while (0)
#define DO_MMAS(buf) do {                                                          \
        _Pragma("unroll")                                                          \
        for (int mt = 0; mt < 4; mt++)                                             \
            _Pragma("unroll")                                                      \
            for (int n2 = 0; n2 < 4; n2++) {                                       \
                mma16816(acc[mt][n2 * 2 + 0],                                      \
                         a[mt][0], a[mt][1], a[mt][2], a[mt][3],                   \
                         b[buf][n2][0], b[buf][n2][1]);                            \
                mma16816(acc[mt][n2 * 2 + 1],                                      \
                         a[mt][0], a[mt][1], a[mt][2], a[mt][3],                   \
                         b[buf][n2][2], b[buf][n2][3]);                            \
            }                                                                      \
    } while (0)

    // prologue: pairs 0 and 1 in flight (2 groups)
    FILL_STAGE(0, 0);
    FILL_STAGE(STAGEB, BK * 2);
    CP_COMMIT();
    FILL_STAGE(2 * STAGEB, 2 * BK * 2);
    FILL_STAGE(3 * STAGEB, 3 * BK * 2);
    CP_COMMIT();

    for (int p = 0; p < PAIRS; ++p) {
        if (p + 1 < PAIRS) { CP_WAIT1(); } else { CP_WAIT0(); }
        __syncthreads();
        if (p + 2 < PAIRS) {
            int c2 = 2 * (p + 2);
            FILL_STAGE((uint32_t)(c2 % NSTG) * STAGEB, c2 * BK * 2);
            FILL_STAGE((uint32_t)((c2 + 1) % NSTG) * STAGEB, (c2 + 1) * BK * 2);
            CP_COMMIT();
        }

        int c0 = 2 * p;
        uint32_t st0 = sb + SM_TILES + (uint32_t)(c0 % NSTG) * STAGEB;
        uint32_t st1 = sb + SM_TILES + (uint32_t)((c0 + 1) % NSTG) * STAGEB;
        uint32_t Aw0 = st0 + a_warp, Bw0 = st0 + b_warp;
        uint32_t Aw1 = st1 + a_warp, Bw1 = st1 + b_warp;

        // software-pipelined pair: only the first load group is latency-exposed
        LOAD_A(Aw0, 0u);
        LOAD_B(0, Bw0, 0u);
        LOAD_B(1, Bw0, 32u);
        DO_MMAS(0);                 // (A c0k0, B c0k0)
        LOAD_A(Aw0, 32u);           // A c0k1
        LOAD_B(0, Bw1, 0u);         // B c1k0 into freed buf0
        DO_MMAS(1);                 // (A c0k1, B c0k1)
        LOAD_A(Aw1, 0u);            // A c1k0
        LOAD_B(1, Bw1, 32u);        // B c1k1
        DO_MMAS(0);                 // (A c1k0, B c1k0)
        LOAD_A(Aw1, 32u);           // A c1k1
        DO_MMAS(1);                 // (A c1k1, B c1k1)
    }

    // ---- epilogue (fp16 scratch) ----
    int qrow = lane >> 2;          // 0..7
    int qcol = (lane & 3) * 2;     // 0,2,4,6
    float2 bias2[8];
#pragma unroll
    for (int nt = 0; nt < 8; nt++) {
        int nc = n0 + wn * 64 + nt * 8 + qcol;
        bias2[nt] = make_float2(be[e * FF + nc], be[e * FF + nc + 1]);
    }
#pragma unroll
    for (int mt = 0; mt < 4; mt++) {
#pragma unroll
        for (int half = 0; half < 2; half++) {
            int mrow = wm * 64 + mt * 16 + half * 8 + qrow;
            if (m0 + mrow < cnt) {
                int entry = s_entry[mrow];
                int tok   = entry & 0xFFFF;
                int slot  = entry >> 16;
                float w   = s_w[mrow];
#pragma unroll
                for (int nt = 0; nt < 8; nt++) {
                    int nc = n0 + wn * 64 + nt * 8 + qcol;
                    float ox = (acc[mt][nt][half * 2 + 0] + bias2[nt].x) * w;
                    float oy = (acc[mt][nt][half * 2 + 1] + bias2[nt].y) * w;
                    *(__half2*)&g_scr[slot][tok][nc] = __floats2half2_rn(ox, oy);
                }
            }
        }
    }
}

// out = scr[0] + scr[1]  (fp16 -> fp32), 8 elements per thread
__global__ void combine_kernel(float* __restrict__ out) {
    size_t j = (size_t)blockIdx.x * blockDim.x + threadIdx.x;  // one uint4 = 8 halves
    uint4 ua = ((const uint4*)g_scr[0])[j];
    uint4 ub = ((const uint4*)g_scr[1])[j];
    float2 a0 = __half22float2(*(__half2*)&ua.x);
    float2 a1 = __half22float2(*(__half2*)&ua.y);
    float2 a2 = __half22float2(*(__half2*)&ua.z);
    float2 a3 = __half22float2(*(__half2*)&ua.w);
    float2 b0 = __half22float2(*(__half2*)&ub.x);
    float2 b1 = __half22float2(*(__half2*)&ub.y);
    float2 b2 = __half22float2(*(__half2*)&ub.z);
    float2 b3 = __half22float2(*(__half2*)&ub.w);
    float4* o = (float4*)out + 2 * j;
    o[0] = make_float4(a0.x + b0.x, a0.y + b0.y, a1.x + b1.x, a1.y + b1.y);
    o[1] = make_float4(a2.x + b2.x, a2.y + b2.y, a3.x + b3.x, a3.y + b3.y);
}

extern "C" void kernel_launch(void* const* d_in, const int* in_sizes, int n_in,
                              void* d_out, int out_size) {
    const float* x  = (const float*)d_in[0];   // (4,4096,1024)
    const float* Wg = (const float*)d_in[1];   // (8,1024)
    const float* bg = (const float*)d_in[2];   // (8,)
    const float* We = (const float*)d_in[3];   // (8,1024,1024)
    const float* be = (const float*)d_in[4];   // (8,1024)
    float* out = (float*)d_out;                // (4,4096,1024) f32

    // zero expert counters via memset node (graph-capturable, no launch)
    void* cnt_addr = nullptr;
    cudaGetSymbolAddress(&cnt_addr, g_cnt);
    cudaMemsetAsync(cnt_addr, 0, NE * sizeof(int));

    gate_transpose_kernel<<<4096, 256>>>(x, Wg, bg, We);

    cudaFuncSetAttribute(expert_gemm_tc, cudaFuncAttributeMaxDynamicSharedMemorySize, SM_TOTAL);
    expert_gemm_tc<<<dim3(NT / BM, FF / BN, NE), 256, SM_TOTAL>>>(be);

    combine_kernel<<<(NT * FF / 8) / 256, 256>>>(out);
}